// round 2
// baseline (speedup 1.0000x reference)
#include <cuda_runtime.h>

#define BATCH 8
#define CH    384
#define NH    8
#define HD    48
#define SEQ   1024
#define O3    1152   // 3*CH

// Scratch (device globals — allocation-free per harness rules)
__device__ float g_qkv[(size_t)BATCH * O3 * SEQ];   // [b][o][p]
__device__ float g_ao [(size_t)BATCH * CH * SEQ];   // attention out, [b][c][p]

// ---------------------------------------------------------------------------
// f32x2 packed-math helpers (sm_100+): one instruction = 2 fp32 FMAs.
// ---------------------------------------------------------------------------
__device__ __forceinline__ unsigned long long f2_pack(float lo, float hi) {
    unsigned long long r;
    asm("mov.b64 %0, {%1, %2};" : "=l"(r) : "f"(lo), "f"(hi));
    return r;
}
__device__ __forceinline__ void f2_unpack(unsigned long long v, float& lo, float& hi) {
    asm("mov.b64 {%0, %1}, %2;" : "=f"(lo), "=f"(hi) : "l"(v));
}
__device__ __forceinline__ unsigned long long f2_fma(unsigned long long a,
                                                     unsigned long long b,
                                                     unsigned long long c) {
    unsigned long long d;
    asm("fma.rn.f32x2 %0, %1, %2, %3;" : "=l"(d) : "l"(a), "l"(b), "l"(c));
    return d;
}
__device__ __forceinline__ unsigned long long f2_add(unsigned long long a,
                                                     unsigned long long b) {
    unsigned long long d;
    asm("add.rn.f32x2 %0, %1, %2;" : "=l"(d) : "l"(a), "l"(b));
    return d;
}

// ---------------------------------------------------------------------------
// 1x1-conv GEMM with FFMA2:  Out[b][o][p] = sum_c W[o][c] * X[b][c][p]
// BM=128, BN=64, BK=16, 128 threads, 8x8 per-thread tile.
// A duplicated in smem (dup along M); N-pairs come free from float4 B frags.
// ---------------------------------------------------------------------------
template<int M_CH, int IS_PROJ>
__global__ __launch_bounds__(128)
void gemm1x1_kernel(const float* __restrict__ W,
                    const float* __restrict__ Xparam,
                    const float* __restrict__ bias,
                    float* __restrict__ Outparam)
{
    __shared__ __align__(16) float As[16][256];  // [k][2*m] duplicated A
    __shared__ __align__(16) float Bs[16][64];   // [k][n]

    const float* Xall = IS_PROJ ? g_ao : Xparam;
    float*       Out  = IS_PROJ ? Outparam : g_qkv;

    const int b  = blockIdx.z;
    const int o0 = blockIdx.y * 128;
    const int p0 = blockIdx.x * 64;
    const float* X = Xall + (size_t)b * CH * SEQ;

    const int tid = threadIdx.x;
    const int ty  = tid >> 3;    // 0..15  (8 M-rows each)
    const int tx  = tid & 7;     // 0..7   (8 N-cols each)

    unsigned long long acc[8][4];
#pragma unroll
    for (int m = 0; m < 8; m++)
#pragma unroll
        for (int n = 0; n < 4; n++) acc[m][n] = 0ull;

    const int bi = tid >> 3;            // 0..15 B k-row
    const int bj = (tid & 7) << 3;      // 0..56 B col base (8 floats)

    for (int k0 = 0; k0 < CH; k0 += 16) {
        // --- load A row (tid-th row of the 128-row tile), 16 k values ---
        const float* wrow = W + (size_t)(o0 + tid) * CH + k0;
#pragma unroll
        for (int i = 0; i < 4; i++) {
            float4 a4 = *reinterpret_cast<const float4*>(wrow + 4 * i);
            // store duplicated pairs; contiguous across warp -> conflict-free
            *reinterpret_cast<float2*>(&As[4 * i + 0][2 * tid]) = make_float2(a4.x, a4.x);
            *reinterpret_cast<float2*>(&As[4 * i + 1][2 * tid]) = make_float2(a4.y, a4.y);
            *reinterpret_cast<float2*>(&As[4 * i + 2][2 * tid]) = make_float2(a4.z, a4.z);
            *reinterpret_cast<float2*>(&As[4 * i + 3][2 * tid]) = make_float2(a4.w, a4.w);
        }
        // --- load B tile rows ---
        const float* xrow = X + (size_t)(k0 + bi) * SEQ + p0 + bj;
        *reinterpret_cast<float4*>(&Bs[bi][bj + 0]) = *reinterpret_cast<const float4*>(xrow + 0);
        *reinterpret_cast<float4*>(&Bs[bi][bj + 4]) = *reinterpret_cast<const float4*>(xrow + 4);
        __syncthreads();

#pragma unroll
        for (int kk = 0; kk < 16; kk++) {
            // A fragment: 8 duplicated pairs = 16 floats = 4 LDS.128
            unsigned long long a2[8];
#pragma unroll
            for (int i = 0; i < 4; i++) {
                ulonglong2 t = *reinterpret_cast<const ulonglong2*>(&As[kk][ty * 16 + 4 * i]);
                a2[2 * i + 0] = t.x;
                a2[2 * i + 1] = t.y;
            }
            // B fragment: 8 floats = 4 natural pairs
            ulonglong2 b01 = *reinterpret_cast<const ulonglong2*>(&Bs[kk][tx * 8 + 0]);
            ulonglong2 b23 = *reinterpret_cast<const ulonglong2*>(&Bs[kk][tx * 8 + 4]);
            unsigned long long bv[4] = {b01.x, b01.y, b23.x, b23.y};
#pragma unroll
            for (int m = 0; m < 8; m++)
#pragma unroll
                for (int n = 0; n < 4; n++)
                    acc[m][n] = f2_fma(a2[m], bv[n], acc[m][n]);
        }
        __syncthreads();
    }

#pragma unroll
    for (int m = 0; m < 8; m++) {
        const int o = o0 + ty * 8 + m;
        float* orow = Out + ((size_t)b * M_CH + o) * SEQ + p0 + tx * 8;
        if (IS_PROJ) {
            unsigned long long bd = f2_pack(bias[o], bias[o]);
            ulonglong2 s0, s1;
            s0.x = f2_add(acc[m][0], bd);  s0.y = f2_add(acc[m][1], bd);
            s1.x = f2_add(acc[m][2], bd);  s1.y = f2_add(acc[m][3], bd);
            *reinterpret_cast<ulonglong2*>(orow + 0) = s0;
            *reinterpret_cast<ulonglong2*>(orow + 4) = s1;
        } else {
            ulonglong2 s0, s1;
            s0.x = acc[m][0];  s0.y = acc[m][1];
            s1.x = acc[m][2];  s1.y = acc[m][3];
            *reinterpret_cast<ulonglong2*>(orow + 0) = s0;
            *reinterpret_cast<ulonglong2*>(orow + 4) = s1;
        }
    }
}

// ---------------------------------------------------------------------------
// Flash-style attention with FFMA2: one query per thread, 32-key tiles.
// Scores/probs are paired along keys; P·V consumes the pairs directly.
// ---------------------------------------------------------------------------
__global__ __launch_bounds__(128)
void attn_kernel()
{
    __shared__ __align__(16) float Ks[HD * 32];   // [d][j] 48x32
    __shared__ __align__(16) float Vs[HD * 32];

    const int bh = blockIdx.y;            // b*8 + h
    const int b  = bh >> 3;
    const int h  = bh & 7;
    const int r  = blockIdx.x * 128 + threadIdx.x;

    const float* qbase = g_qkv + ((size_t)b * O3 +          h * HD) * SEQ;
    const float* kbase = g_qkv + ((size_t)b * O3 + CH     + h * HD) * SEQ;
    const float* vbase = g_qkv + ((size_t)b * O3 + 2 * CH + h * HD) * SEQ;

    const float scale = 0.14433756729740643f;   // 48^-0.5

    float q[HD];
#pragma unroll
    for (int d = 0; d < HD; d++) q[d] = qbase[(size_t)d * SEQ + r] * scale;

    float o[HD];
#pragma unroll
    for (int d = 0; d < HD; d++) o[d] = 0.f;

    float mrun = -1e30f;
    float lrun = 0.f;

    for (int j0 = 0; j0 < SEQ; j0 += 32) {
        __syncthreads();
        {
            float4* K4 = reinterpret_cast<float4*>(Ks);
            float4* V4 = reinterpret_cast<float4*>(Vs);
            for (int idx = threadIdx.x; idx < HD * 8; idx += 128) {
                int dd = idx >> 3;
                int j4 = idx & 7;
                K4[idx] = *reinterpret_cast<const float4*>(kbase + (size_t)dd * SEQ + j0 + (j4 << 2));
                V4[idx] = *reinterpret_cast<const float4*>(vbase + (size_t)dd * SEQ + j0 + (j4 << 2));
            }
        }
        __syncthreads();

        // ---- scores: s2[j2] = sum_d q[d] * K[d][2*j2 .. 2*j2+1] ----
        unsigned long long s2[16];
#pragma unroll
        for (int j2 = 0; j2 < 16; j2++) s2[j2] = 0ull;
#pragma unroll
        for (int d = 0; d < HD; d++) {
            unsigned long long qd2 = f2_pack(q[d], q[d]);
            const ulonglong2* krow = reinterpret_cast<const ulonglong2*>(&Ks[d * 32]);
#pragma unroll
            for (int j4 = 0; j4 < 8; j4++) {
                ulonglong2 k2 = krow[j4];            // broadcast LDS.128
                s2[2 * j4 + 0] = f2_fma(qd2, k2.x, s2[2 * j4 + 0]);
                s2[2 * j4 + 1] = f2_fma(qd2, k2.y, s2[2 * j4 + 1]);
            }
        }

        // ---- online softmax on unpacked scores ----
        float sv[32];
#pragma unroll
        for (int j2 = 0; j2 < 16; j2++) f2_unpack(s2[j2], sv[2 * j2], sv[2 * j2 + 1]);

        float mb = mrun;
#pragma unroll
        for (int j = 0; j < 32; j++) mb = fmaxf(mb, sv[j]);
        const float f = __expf(mrun - mb);
        mrun = mb;
        lrun *= f;
#pragma unroll
        for (int j = 0; j < 32; j++) {
            sv[j] = __expf(sv[j] - mb);
            lrun += sv[j];
        }
#pragma unroll
        for (int j2 = 0; j2 < 16; j2++) s2[j2] = f2_pack(sv[2 * j2], sv[2 * j2 + 1]);

        // ---- o[d] = o[d]*f + sum_j p[j] * V[d][j]  (pairs along j) ----
#pragma unroll
        for (int d = 0; d < HD; d++) {
            unsigned long long acc2 = 0ull;
            const ulonglong2* vrow = reinterpret_cast<const ulonglong2*>(&Vs[d * 32]);
#pragma unroll
            for (int j4 = 0; j4 < 8; j4++) {
                ulonglong2 v2 = vrow[j4];            // broadcast LDS.128
                acc2 = f2_fma(s2[2 * j4 + 0], v2.x, acc2);
                acc2 = f2_fma(s2[2 * j4 + 1], v2.y, acc2);
            }
            float lo, hi;
            f2_unpack(acc2, lo, hi);
            o[d] = fmaf(o[d], f, lo + hi);
        }
    }

    const float inv = 1.f / lrun;
    float* obase = g_ao + (size_t)bh * HD * SEQ + r;
#pragma unroll
    for (int d = 0; d < HD; d++) obase[(size_t)d * SEQ] = o[d] * inv;
}

// ---------------------------------------------------------------------------
extern "C" void kernel_launch(void* const* d_in, const int* in_sizes, int n_in,
                              void* d_out, int out_size)
{
    const float* x      = (const float*)d_in[0];   // [8,384,32,32]
    const float* w_qkv  = (const float*)d_in[1];   // [1152,384]
    const float* w_proj = (const float*)d_in[2];   // [384,384]
    const float* b_proj = (const float*)d_in[3];   // [384]
    float* out = (float*)d_out;                    // [8,384,32,32]

    gemm1x1_kernel<O3, 0><<<dim3(SEQ / 64, O3 / 128, BATCH), 128>>>(w_qkv, x, nullptr, nullptr);
    attn_kernel<<<dim3(SEQ / 128, BATCH * NH), 128>>>();
    gemm1x1_kernel<CH, 1><<<dim3(SEQ / 64, CH / 128, BATCH), 128>>>(w_proj, nullptr, b_proj, out);
}

// round 3
// speedup vs baseline: 6.3791x; 6.3791x over previous
#include <cuda_runtime.h>
#include <cuda_fp16.h>
#include <cstdint>

#define BATCH 8
#define CH    384
#define NH    8
#define HD    48
#define SEQ   1024
#define O3    1152   // 3*CH

// fp16 scratch (device globals — allocation-free per harness rules)
__device__ __align__(16) __half g_qkv_h[(size_t)BATCH * O3 * SEQ];  // [b][o][p]
__device__ __align__(16) __half g_ao_h [(size_t)BATCH * CH * SEQ];  // [b][c][p]

// ---------------------------------------------------------------------------
// PTX helpers
// ---------------------------------------------------------------------------
__device__ __forceinline__ uint32_t cvta_s(const void* p) {
    return (uint32_t)__cvta_generic_to_shared(p);
}
__device__ __forceinline__ void ldmx4(uint32_t* r, uint32_t a) {
    asm volatile("ldmatrix.sync.aligned.m8n8.x4.shared.b16 {%0,%1,%2,%3},[%4];"
        : "=r"(r[0]), "=r"(r[1]), "=r"(r[2]), "=r"(r[3]) : "r"(a));
}
__device__ __forceinline__ void ldmx4t(uint32_t* r, uint32_t a) {
    asm volatile("ldmatrix.sync.aligned.m8n8.x4.trans.shared.b16 {%0,%1,%2,%3},[%4];"
        : "=r"(r[0]), "=r"(r[1]), "=r"(r[2]), "=r"(r[3]) : "r"(a));
}
__device__ __forceinline__ void mma16816(float* c, const uint32_t* a,
                                         uint32_t b0, uint32_t b1) {
    asm volatile(
        "mma.sync.aligned.m16n8k16.row.col.f32.f16.f16.f32 "
        "{%0,%1,%2,%3},{%4,%5,%6,%7},{%8,%9},{%0,%1,%2,%3};"
        : "+f"(c[0]), "+f"(c[1]), "+f"(c[2]), "+f"(c[3])
        : "r"(a[0]), "r"(a[1]), "r"(a[2]), "r"(a[3]), "r"(b0), "r"(b1));
}
__device__ __forceinline__ uint32_t pack_h2(float lo, float hi) {
    __half2 h = __floats2half2_rn(lo, hi);
    return *reinterpret_cast<uint32_t*>(&h);
}

// ---------------------------------------------------------------------------
// 1x1-conv GEMM on tensor cores: C[b][o][p] = sum_c W[o][c] * X[b][c][p]
// BM=128 BN=128 BK=32, 256 threads (8 warps, 4x2), warp tile 32x64.
// IS_PROJ=0: A=w_qkv fp32, B=x fp32 -> convert; out fp16 to g_qkv_h.
// IS_PROJ=1: A=w_proj fp32; B=g_ao_h fp16; out fp32 + bias to d_out.
// ---------------------------------------------------------------------------
template<int M_CH, int IS_PROJ>
__global__ __launch_bounds__(256)
void gemm_h_kernel(const float* __restrict__ W,
                   const float* __restrict__ X32,
                   const float* __restrict__ bias,
                   float* __restrict__ Out32)
{
    constexpr int BM = 128, BN = 128, BK = 32;
    constexpr int LDA = BK + 8;   // 40 halves -> 80B row stride (conflict-free ldmatrix)
    constexpr int LDB = BN + 8;   // 136 halves -> 272B

    __shared__ __align__(16) __half As[BM * LDA];
    __shared__ __align__(16) __half Bs[BK * LDB];

    const int b   = blockIdx.z;
    const int o0  = blockIdx.y * BM;
    const int p0  = blockIdx.x * BN;
    const int tid = threadIdx.x;
    const int warp = tid >> 5, lane = tid & 31;
    const int wm = warp >> 1, wn = warp & 1;   // 4x2 warp grid

    float acc[2][8][4] = {};

    // A-fragment ldmatrix address components (row-major [m][k] smem)
    const int a_r = lane & 15;            // + m-tile base
    const int a_c = 8 * (lane >> 4);      // + kk
    // B-fragment (trans) address components (smem [k][n])
    const int b_r = (lane & 7) + 8 * ((lane >> 3) & 1);   // + kk
    const int b_c = 8 * (lane >> 4);                      // + n-tile-pair base

    for (int k0 = 0; k0 < CH; k0 += BK) {
        // ---- A tile: 128x32 fp32 -> fp16 smem ----
        {
            const int row = tid >> 1, cb = (tid & 1) * 16;
            const float* wrow = W + (size_t)(o0 + row) * CH + k0 + cb;
            __half* adst = As + row * LDA + cb;
#pragma unroll
            for (int i = 0; i < 4; i++) {
                float4 v = *reinterpret_cast<const float4*>(wrow + 4 * i);
                *reinterpret_cast<uint2*>(adst + 4 * i) =
                    make_uint2(pack_h2(v.x, v.y), pack_h2(v.z, v.w));
            }
        }
        // ---- B tile: 32x128 ----
        {
            const int row = tid >> 3, cb = (tid & 7) * 16;
            __half* bdst = Bs + row * LDB + cb;
            if (!IS_PROJ) {
                const float* xrow = X32 + (size_t)b * CH * SEQ
                                  + (size_t)(k0 + row) * SEQ + p0 + cb;
#pragma unroll
                for (int i = 0; i < 4; i++) {
                    float4 v = *reinterpret_cast<const float4*>(xrow + 4 * i);
                    *reinterpret_cast<uint2*>(bdst + 4 * i) =
                        make_uint2(pack_h2(v.x, v.y), pack_h2(v.z, v.w));
                }
            } else {
                const __half* xrow = g_ao_h + (size_t)b * CH * SEQ
                                   + (size_t)(k0 + row) * SEQ + p0 + cb;
                *reinterpret_cast<uint4*>(bdst + 0) = *reinterpret_cast<const uint4*>(xrow + 0);
                *reinterpret_cast<uint4*>(bdst + 8) = *reinterpret_cast<const uint4*>(xrow + 8);
            }
        }
        __syncthreads();

#pragma unroll
        for (int kk = 0; kk < BK; kk += 16) {
            uint32_t af[2][4];
#pragma unroll
            for (int mt = 0; mt < 2; mt++)
                ldmx4(af[mt], cvta_s(As + (wm * 32 + mt * 16 + a_r) * LDA + kk + a_c));
            uint32_t bf[8][2];
#pragma unroll
            for (int ntp = 0; ntp < 4; ntp++) {
                uint32_t r[4];
                ldmx4t(r, cvta_s(Bs + (kk + b_r) * LDB + wn * 64 + ntp * 16 + b_c));
                bf[2 * ntp][0] = r[0]; bf[2 * ntp][1] = r[1];
                bf[2 * ntp + 1][0] = r[2]; bf[2 * ntp + 1][1] = r[3];
            }
#pragma unroll
            for (int mt = 0; mt < 2; mt++)
#pragma unroll
                for (int nt = 0; nt < 8; nt++)
                    mma16816(acc[mt][nt], af[mt], bf[nt][0], bf[nt][1]);
        }
        __syncthreads();
    }

    // ---- epilogue ----
    const int g = lane >> 2, tig = lane & 3;
#pragma unroll
    for (int mt = 0; mt < 2; mt++) {
        const int o_r = o0 + wm * 32 + mt * 16 + g;
#pragma unroll
        for (int nt = 0; nt < 8; nt++) {
            const int p_c = p0 + wn * 64 + nt * 8 + 2 * tig;
            if (!IS_PROJ) {
                __half* dst = g_qkv_h + ((size_t)b * O3 + o_r) * SEQ + p_c;
                *reinterpret_cast<uint32_t*>(dst) =
                    pack_h2(acc[mt][nt][0], acc[mt][nt][1]);
                *reinterpret_cast<uint32_t*>(dst + 8 * SEQ) =
                    pack_h2(acc[mt][nt][2], acc[mt][nt][3]);
            } else {
                const float bv0 = bias[o_r], bv1 = bias[o_r + 8];
                float* dst = Out32 + ((size_t)b * M_CH + o_r) * SEQ + p_c;
                *reinterpret_cast<float2*>(dst) =
                    make_float2(acc[mt][nt][0] + bv0, acc[mt][nt][1] + bv0);
                *reinterpret_cast<float2*>(dst + 8 * SEQ) =
                    make_float2(acc[mt][nt][2] + bv1, acc[mt][nt][3] + bv1);
            }
        }
    }
}

// ---------------------------------------------------------------------------
// Flash attention on tensor cores. Per CTA: one (b,h), 128 queries
// (8 warps x 16 rows). Key tiles of 64. All operands fp16, accum fp32.
// ---------------------------------------------------------------------------
__global__ __launch_bounds__(256)
void attn_h_kernel()
{
    constexpr int LDQ = 136;  // 128+8 halves
    constexpr int LDK = 72;   // 64+8 halves

    __shared__ __align__(16) __half Qs[HD * LDQ];
    __shared__ __align__(16) __half Ks[HD * LDK];
    __shared__ __align__(16) __half Vs[HD * LDK];

    const int bh = blockIdx.y, qb = blockIdx.x;
    const int tid = threadIdx.x, warp = tid >> 5, lane = tid & 31;
    const int b = bh >> 3, h = bh & 7;

    const __half* qbase = g_qkv_h + ((size_t)b * O3 + h * HD) * SEQ;
    const __half* kbase = qbase + (size_t)CH * SEQ;
    const __half* vbase = qbase + (size_t)2 * CH * SEQ;
    const int q0g = qb * 128;

    const float scale = 0.14433756729740643f;   // 48^-0.5

    // ---- load Q tile [48][128] ----
    for (int i = tid; i < HD * 16; i += 256) {
        int d = i >> 4, c = (i & 15) * 8;
        *reinterpret_cast<uint4*>(Qs + d * LDQ + c) =
            *reinterpret_cast<const uint4*>(qbase + (size_t)d * SEQ + q0g + c);
    }
    __syncthreads();

    // ---- Q A-fragments (trans-load from [d][q] storage), held in regs ----
    uint32_t qa[3][4];
    {
        const int m0 = warp * 16;
        const int r_off = (lane & 7) + 8 * (lane >> 4);
        const int c_off = m0 + 8 * ((lane >> 3) & 1);
#pragma unroll
        for (int kt = 0; kt < 3; kt++)
            ldmx4t(qa[kt], cvta_s(Qs + (kt * 16 + r_off) * LDQ + c_off));
    }
    __syncthreads();

    float m0r = -1e30f, m1r = -1e30f;   // running max (scaled units), rows g / g+8
    float l0r = 0.f, l1r = 0.f;         // per-thread partial row sums
    float oa[6][4] = {};

    const int kb_r = (lane & 7) + 8 * ((lane >> 3) & 1);  // K trans-ldm row comp
    const int kb_c = 8 * (lane >> 4);
    const int vb_r = (lane & 7) + 8 * (lane >> 4);        // V ldm row comp
    const int vb_c = 8 * ((lane >> 3) & 1);

    for (int j0 = 0; j0 < SEQ; j0 += 64) {
        // ---- load K/V tiles [48][64] ----
        for (int i = tid; i < HD * 8; i += 256) {
            int d = i >> 3, c = (i & 7) * 8;
            *reinterpret_cast<uint4*>(Ks + d * LDK + c) =
                *reinterpret_cast<const uint4*>(kbase + (size_t)d * SEQ + j0 + c);
            *reinterpret_cast<uint4*>(Vs + d * LDK + c) =
                *reinterpret_cast<const uint4*>(vbase + (size_t)d * SEQ + j0 + c);
        }
        __syncthreads();

        // ---- S = Q K^T : 8 n-tiles of 8 keys ----
        float s[8][4] = {};
#pragma unroll
        for (int kt = 0; kt < 3; kt++) {
            uint32_t bf[8][2];
#pragma unroll
            for (int ntp = 0; ntp < 4; ntp++) {
                uint32_t r[4];
                ldmx4t(r, cvta_s(Ks + (kt * 16 + kb_r) * LDK + ntp * 16 + kb_c));
                bf[2 * ntp][0] = r[0]; bf[2 * ntp][1] = r[1];
                bf[2 * ntp + 1][0] = r[2]; bf[2 * ntp + 1][1] = r[3];
            }
#pragma unroll
            for (int nt = 0; nt < 8; nt++)
                mma16816(s[nt], qa[kt], bf[nt][0], bf[nt][1]);
        }

        // ---- online softmax (rows g and g+8; 4 lanes per row) ----
        float mx0 = -1e30f, mx1 = -1e30f;
#pragma unroll
        for (int nt = 0; nt < 8; nt++) {
            mx0 = fmaxf(mx0, fmaxf(s[nt][0], s[nt][1]));
            mx1 = fmaxf(mx1, fmaxf(s[nt][2], s[nt][3]));
        }
        mx0 = fmaxf(mx0, __shfl_xor_sync(0xffffffffu, mx0, 1));
        mx0 = fmaxf(mx0, __shfl_xor_sync(0xffffffffu, mx0, 2));
        mx1 = fmaxf(mx1, __shfl_xor_sync(0xffffffffu, mx1, 1));
        mx1 = fmaxf(mx1, __shfl_xor_sync(0xffffffffu, mx1, 2));

        const float mn0 = fmaxf(m0r, mx0 * scale);
        const float mn1 = fmaxf(m1r, mx1 * scale);
        const float f0 = __expf(m0r - mn0);
        const float f1 = __expf(m1r - mn1);
        m0r = mn0; m1r = mn1;

        float sum0 = 0.f, sum1 = 0.f;
#pragma unroll
        for (int nt = 0; nt < 8; nt++) {
            s[nt][0] = __expf(fmaf(s[nt][0], scale, -mn0));
            s[nt][1] = __expf(fmaf(s[nt][1], scale, -mn0));
            s[nt][2] = __expf(fmaf(s[nt][2], scale, -mn1));
            s[nt][3] = __expf(fmaf(s[nt][3], scale, -mn1));
            sum0 += s[nt][0] + s[nt][1];
            sum1 += s[nt][2] + s[nt][3];
        }
        l0r = l0r * f0 + sum0;
        l1r = l1r * f1 + sum1;
#pragma unroll
        for (int nt2 = 0; nt2 < 6; nt2++) {
            oa[nt2][0] *= f0; oa[nt2][1] *= f0;
            oa[nt2][2] *= f1; oa[nt2][3] *= f1;
        }

        // ---- O += P V : repack P C-frags -> A-frags; V via non-trans ldm ----
#pragma unroll
        for (int t = 0; t < 4; t++) {
            uint32_t pa[4];
            pa[0] = pack_h2(s[2 * t][0],     s[2 * t][1]);
            pa[1] = pack_h2(s[2 * t][2],     s[2 * t][3]);
            pa[2] = pack_h2(s[2 * t + 1][0], s[2 * t + 1][1]);
            pa[3] = pack_h2(s[2 * t + 1][2], s[2 * t + 1][3]);
#pragma unroll
            for (int np = 0; np < 3; np++) {
                uint32_t r[4];
                ldmx4(r, cvta_s(Vs + (np * 16 + vb_r) * LDK + t * 16 + vb_c));
                mma16816(oa[2 * np],     pa, r[0], r[1]);
                mma16816(oa[2 * np + 1], pa, r[2], r[3]);
            }
        }
        __syncthreads();
    }

    // ---- epilogue: normalize, write fp16 [c][p] ----
    l0r += __shfl_xor_sync(0xffffffffu, l0r, 1);
    l0r += __shfl_xor_sync(0xffffffffu, l0r, 2);
    l1r += __shfl_xor_sync(0xffffffffu, l1r, 1);
    l1r += __shfl_xor_sync(0xffffffffu, l1r, 2);
    const float inv0 = 1.f / l0r, inv1 = 1.f / l1r;

    const int g = lane >> 2, tig = lane & 3;
    const int q_r = q0g + warp * 16 + g;
#pragma unroll
    for (int nt2 = 0; nt2 < 6; nt2++) {
        const int d = nt2 * 8 + 2 * tig;
        __half* dst = g_ao_h + ((size_t)bh * HD + d) * SEQ;
        dst[q_r]           = __float2half(oa[nt2][0] * inv0);
        dst[SEQ + q_r]     = __float2half(oa[nt2][1] * inv0);
        dst[q_r + 8]       = __float2half(oa[nt2][2] * inv1);
        dst[SEQ + q_r + 8] = __float2half(oa[nt2][3] * inv1);
    }
}

// ---------------------------------------------------------------------------
extern "C" void kernel_launch(void* const* d_in, const int* in_sizes, int n_in,
                              void* d_out, int out_size)
{
    const float* x      = (const float*)d_in[0];   // [8,384,32,32]
    const float* w_qkv  = (const float*)d_in[1];   // [1152,384]
    const float* w_proj = (const float*)d_in[2];   // [384,384]
    const float* b_proj = (const float*)d_in[3];   // [384]
    float* out = (float*)d_out;                    // [8,384,32,32]

    gemm_h_kernel<O3, 0><<<dim3(SEQ / 128, O3 / 128, BATCH), 256>>>(w_qkv, x, nullptr, nullptr);
    attn_h_kernel<<<dim3(SEQ / 128, BATCH * NH), 256>>>();
    gemm_h_kernel<CH, 1><<<dim3(SEQ / 128, CH / 128, BATCH), 256>>>(w_proj, nullptr, b_proj, out);
}

// round 4
// speedup vs baseline: 8.7676x; 1.3744x over previous
#include <cuda_runtime.h>
#include <cuda_fp16.h>
#include <cstdint>

#define BATCH 8
#define CH    384
#define NH    8
#define HD    48
#define SEQ   1024
#define O3    1152   // 3*CH

// fp16 scratch (device globals — allocation-free per harness rules)
__device__ __align__(16) __half g_x_h    [(size_t)BATCH * CH * SEQ];  // x fp16 [b][c][p]
__device__ __align__(16) __half g_wqkv_h [(size_t)O3 * CH];           // w_qkv fp16
__device__ __align__(16) __half g_wproj_h[(size_t)CH * CH];           // w_proj fp16
__device__ __align__(16) __half g_qkv_h  [(size_t)BATCH * O3 * SEQ];  // [b][o][p]
__device__ __align__(16) __half g_ao_h   [(size_t)BATCH * CH * SEQ];  // [b][c][p]

// ---------------------------------------------------------------------------
// PTX helpers
// ---------------------------------------------------------------------------
__device__ __forceinline__ uint32_t cvta_s(const void* p) {
    return (uint32_t)__cvta_generic_to_shared(p);
}
__device__ __forceinline__ void ldmx4(uint32_t* r, uint32_t a) {
    asm volatile("ldmatrix.sync.aligned.m8n8.x4.shared.b16 {%0,%1,%2,%3},[%4];"
        : "=r"(r[0]), "=r"(r[1]), "=r"(r[2]), "=r"(r[3]) : "r"(a));
}
__device__ __forceinline__ void ldmx4t(uint32_t* r, uint32_t a) {
    asm volatile("ldmatrix.sync.aligned.m8n8.x4.trans.shared.b16 {%0,%1,%2,%3},[%4];"
        : "=r"(r[0]), "=r"(r[1]), "=r"(r[2]), "=r"(r[3]) : "r"(a));
}
__device__ __forceinline__ void mma16816(float* c, const uint32_t* a,
                                         uint32_t b0, uint32_t b1) {
    asm volatile(
        "mma.sync.aligned.m16n8k16.row.col.f32.f16.f16.f32 "
        "{%0,%1,%2,%3},{%4,%5,%6,%7},{%8,%9},{%0,%1,%2,%3};"
        : "+f"(c[0]), "+f"(c[1]), "+f"(c[2]), "+f"(c[3])
        : "r"(a[0]), "r"(a[1]), "r"(a[2]), "r"(a[3]), "r"(b0), "r"(b1));
}
__device__ __forceinline__ uint32_t pack_h2(float lo, float hi) {
    __half2 h = __floats2half2_rn(lo, hi);
    return *reinterpret_cast<uint32_t*>(&h);
}
__device__ __forceinline__ void cp16(uint32_t s, const void* g) {
    asm volatile("cp.async.cg.shared.global [%0], [%1], 16;" :: "r"(s), "l"(g));
}
__device__ __forceinline__ void cp_commit() {
    asm volatile("cp.async.commit_group;");
}
__device__ __forceinline__ void cp_wait1() {
    asm volatile("cp.async.wait_group 1;");
}
__device__ __forceinline__ void cp_wait0() {
    asm volatile("cp.async.wait_group 0;");
}

// ---------------------------------------------------------------------------
// fp32 -> fp16 pre-conversion of x, w_qkv, w_proj (one launch)
// ---------------------------------------------------------------------------
#define N4_X  (BATCH * CH * SEQ / 4)   // 786432
#define N4_WQ (O3 * CH / 4)            // 110592
#define N4_WP (CH * CH / 4)            // 36864
#define N4_ALL (N4_X + N4_WQ + N4_WP)

__global__ __launch_bounds__(256)
void cvt_kernel(const float* __restrict__ x,
                const float* __restrict__ wq,
                const float* __restrict__ wp)
{
    int i = blockIdx.x * 256 + threadIdx.x;
    if (i >= N4_ALL) return;
    const float4* src;
    __half* dst;
    int off;
    if (i < N4_X)              { src = (const float4*)x;  dst = g_x_h;     off = i; }
    else if (i < N4_X + N4_WQ) { src = (const float4*)wq; dst = g_wqkv_h;  off = i - N4_X; }
    else                       { src = (const float4*)wp; dst = g_wproj_h; off = i - N4_X - N4_WQ; }
    float4 v = src[off];
    *reinterpret_cast<uint2*>(dst + 4 * (size_t)off) =
        make_uint2(pack_h2(v.x, v.y), pack_h2(v.z, v.w));
}

// ---------------------------------------------------------------------------
// fp16 GEMM, cp.async 2-stage pipeline.
// C[b][o][p] = sum_c A[o][c] * B[b][c][p]
// BM=128 BN=128 BK=32, 256 threads (8 warps 4x2), warp tile 32x64.
// ---------------------------------------------------------------------------
template<int M_CH, int IS_PROJ>
__global__ __launch_bounds__(256)
void gemm_h_kernel(const float* __restrict__ bias, float* __restrict__ Out32)
{
    constexpr int BM = 128, BN = 128, BK = 32;
    constexpr int LDA = BK + 8;   // 40 halves
    constexpr int LDB = BN + 8;   // 136 halves
    constexpr int NIT = CH / BK;  // 12

    __shared__ __align__(16) __half As[2][BM * LDA];
    __shared__ __align__(16) __half Bs[2][BK * LDB];

    const __half* gA = IS_PROJ ? g_wproj_h : g_wqkv_h;
    const __half* gB = (IS_PROJ ? g_ao_h : g_x_h) + (size_t)blockIdx.z * CH * SEQ;

    const int b   = blockIdx.z;
    const int o0  = blockIdx.y * BM;
    const int p0  = blockIdx.x * BN;
    const int tid = threadIdx.x;
    const int warp = tid >> 5, lane = tid & 31;
    const int wm = warp >> 1, wn = warp & 1;

    // cp.async load coords
    const int ar = tid >> 2, ac = (tid & 3) * 8;   // A: rows ar, ar+64; 8-half chunk
    const int br = tid >> 3, bc = (tid & 7) * 8;   // B: row br; chunks bc, bc+64

    // ldmatrix fragment coords (identical to R2)
    const int a_r = lane & 15;
    const int a_c = 8 * (lane >> 4);
    const int b_r = (lane & 7) + 8 * ((lane >> 3) & 1);
    const int b_c = 8 * (lane >> 4);

    float acc[2][8][4] = {};

    auto load_stage = [&](int st, int k0) {
        cp16(cvta_s(&As[st][ar * LDA + ac]),        gA + (size_t)(o0 + ar) * CH + k0 + ac);
        cp16(cvta_s(&As[st][(ar + 64) * LDA + ac]), gA + (size_t)(o0 + ar + 64) * CH + k0 + ac);
        const __half* brow = gB + (size_t)(k0 + br) * SEQ + p0;
        cp16(cvta_s(&Bs[st][br * LDB + bc]),      brow + bc);
        cp16(cvta_s(&Bs[st][br * LDB + bc + 64]), brow + bc + 64);
        cp_commit();
    };

    load_stage(0, 0);

    for (int it = 0; it < NIT; it++) {
        if (it + 1 < NIT) { load_stage((it + 1) & 1, (it + 1) * BK); cp_wait1(); }
        else              { cp_wait0(); }
        __syncthreads();

        const __half* Ac = As[it & 1];
        const __half* Bc = Bs[it & 1];
#pragma unroll
        for (int kk = 0; kk < BK; kk += 16) {
            uint32_t af[2][4];
#pragma unroll
            for (int mt = 0; mt < 2; mt++)
                ldmx4(af[mt], cvta_s(Ac + (wm * 32 + mt * 16 + a_r) * LDA + kk + a_c));
            uint32_t bf[8][2];
#pragma unroll
            for (int ntp = 0; ntp < 4; ntp++) {
                uint32_t r[4];
                ldmx4t(r, cvta_s(Bc + (kk + b_r) * LDB + wn * 64 + ntp * 16 + b_c));
                bf[2 * ntp][0] = r[0]; bf[2 * ntp][1] = r[1];
                bf[2 * ntp + 1][0] = r[2]; bf[2 * ntp + 1][1] = r[3];
            }
#pragma unroll
            for (int mt = 0; mt < 2; mt++)
#pragma unroll
                for (int nt = 0; nt < 8; nt++)
                    mma16816(acc[mt][nt], af[mt], bf[nt][0], bf[nt][1]);
        }
        __syncthreads();
    }

    // ---- epilogue ----
    const int g = lane >> 2, tig = lane & 3;
#pragma unroll
    for (int mt = 0; mt < 2; mt++) {
        const int o_r = o0 + wm * 32 + mt * 16 + g;
#pragma unroll
        for (int nt = 0; nt < 8; nt++) {
            const int p_c = p0 + wn * 64 + nt * 8 + 2 * tig;
            if (!IS_PROJ) {
                __half* dst = g_qkv_h + ((size_t)b * O3 + o_r) * SEQ + p_c;
                *reinterpret_cast<uint32_t*>(dst) =
                    pack_h2(acc[mt][nt][0], acc[mt][nt][1]);
                *reinterpret_cast<uint32_t*>(dst + 8 * SEQ) =
                    pack_h2(acc[mt][nt][2], acc[mt][nt][3]);
            } else {
                const float bv0 = bias[o_r], bv1 = bias[o_r + 8];
                float* dst = Out32 + ((size_t)b * M_CH + o_r) * SEQ + p_c;
                *reinterpret_cast<float2*>(dst) =
                    make_float2(acc[mt][nt][0] + bv0, acc[mt][nt][1] + bv0);
                *reinterpret_cast<float2*>(dst + 8 * SEQ) =
                    make_float2(acc[mt][nt][2] + bv1, acc[mt][nt][3] + bv1);
            }
        }
    }
}

// ---------------------------------------------------------------------------
// Flash attention on tensor cores, cp.async double-buffered K/V tiles.
// Per CTA: one (b,h), 128 queries (8 warps x 16 rows), key tiles of 64.
// ---------------------------------------------------------------------------
__global__ __launch_bounds__(256)
void attn_h_kernel()
{
    constexpr int LDQ = 136;  // 128+8 halves
    constexpr int LDK = 72;   // 64+8 halves
    constexpr int NJT = SEQ / 64;   // 16

    __shared__ __align__(16) __half Qs[HD * LDQ];
    __shared__ __align__(16) __half Ks[2][HD * LDK];
    __shared__ __align__(16) __half Vs[2][HD * LDK];

    const int bh = blockIdx.y, qb = blockIdx.x;
    const int tid = threadIdx.x, warp = tid >> 5, lane = tid & 31;
    const int b = bh >> 3, h = bh & 7;

    const __half* qbase = g_qkv_h + ((size_t)b * O3 + h * HD) * SEQ;
    const __half* kbase = qbase + (size_t)CH * SEQ;
    const __half* vbase = qbase + (size_t)2 * CH * SEQ;
    const int q0g = qb * 128;

    const float scale = 0.14433756729740643f;   // 48^-0.5

    // K/V stage loader: 48 rows x 8 chunks (16B) each for K and V = 768 chunks.
    auto load_kv = [&](int st, int j0) {
#pragma unroll
        for (int rep = 0; rep < 3; rep++) {
            int i = tid + 256 * rep;
            if (i < HD * 8) {
                int d = i >> 3, c = (i & 7) * 8;
                cp16(cvta_s(&Ks[st][d * LDK + c]), kbase + (size_t)d * SEQ + j0 + c);
            } else {
                int i2 = i - HD * 8;
                int d = i2 >> 3, c = (i2 & 7) * 8;
                cp16(cvta_s(&Vs[st][d * LDK + c]), vbase + (size_t)d * SEQ + j0 + c);
            }
        }
        cp_commit();
    };

    load_kv(0, 0);

    // ---- load Q tile [48][128] (plain loads, overlapped with K/V cp.async) ----
    for (int i = tid; i < HD * 16; i += 256) {
        int d = i >> 4, c = (i & 15) * 8;
        *reinterpret_cast<uint4*>(Qs + d * LDQ + c) =
            *reinterpret_cast<const uint4*>(qbase + (size_t)d * SEQ + q0g + c);
    }
    __syncthreads();

    // ---- Q A-fragments held in regs ----
    uint32_t qa[3][4];
    {
        const int r_off = (lane & 7) + 8 * (lane >> 4);
        const int c_off = warp * 16 + 8 * ((lane >> 3) & 1);
#pragma unroll
        for (int kt = 0; kt < 3; kt++)
            ldmx4t(qa[kt], cvta_s(Qs + (kt * 16 + r_off) * LDQ + c_off));
    }

    float m0r = -1e30f, m1r = -1e30f;
    float l0r = 0.f, l1r = 0.f;
    float oa[6][4] = {};

    const int kb_r = (lane & 7) + 8 * ((lane >> 3) & 1);
    const int kb_c = 8 * (lane >> 4);
    const int vb_r = (lane & 7) + 8 * (lane >> 4);
    const int vb_c = 8 * ((lane >> 3) & 1);

    for (int it = 0; it < NJT; it++) {
        if (it + 1 < NJT) { load_kv((it + 1) & 1, (it + 1) * 64); cp_wait1(); }
        else              { cp_wait0(); }
        __syncthreads();

        const __half* Kc = Ks[it & 1];
        const __half* Vc = Vs[it & 1];

        // ---- S = Q K^T ----
        float s[8][4] = {};
#pragma unroll
        for (int kt = 0; kt < 3; kt++) {
            uint32_t bf[8][2];
#pragma unroll
            for (int ntp = 0; ntp < 4; ntp++) {
                uint32_t r[4];
                ldmx4t(r, cvta_s(Kc + (kt * 16 + kb_r) * LDK + ntp * 16 + kb_c));
                bf[2 * ntp][0] = r[0]; bf[2 * ntp][1] = r[1];
                bf[2 * ntp + 1][0] = r[2]; bf[2 * ntp + 1][1] = r[3];
            }
#pragma unroll
            for (int nt = 0; nt < 8; nt++)
                mma16816(s[nt], qa[kt], bf[nt][0], bf[nt][1]);
        }

        // ---- online softmax ----
        float mx0 = -1e30f, mx1 = -1e30f;
#pragma unroll
        for (int nt = 0; nt < 8; nt++) {
            mx0 = fmaxf(mx0, fmaxf(s[nt][0], s[nt][1]));
            mx1 = fmaxf(mx1, fmaxf(s[nt][2], s[nt][3]));
        }
        mx0 = fmaxf(mx0, __shfl_xor_sync(0xffffffffu, mx0, 1));
        mx0 = fmaxf(mx0, __shfl_xor_sync(0xffffffffu, mx0, 2));
        mx1 = fmaxf(mx1, __shfl_xor_sync(0xffffffffu, mx1, 1));
        mx1 = fmaxf(mx1, __shfl_xor_sync(0xffffffffu, mx1, 2));

        const float mn0 = fmaxf(m0r, mx0 * scale);
        const float mn1 = fmaxf(m1r, mx1 * scale);
        const float f0 = __expf(m0r - mn0);
        const float f1 = __expf(m1r - mn1);
        m0r = mn0; m1r = mn1;

        float sum0 = 0.f, sum1 = 0.f;
#pragma unroll
        for (int nt = 0; nt < 8; nt++) {
            s[nt][0] = __expf(fmaf(s[nt][0], scale, -mn0));
            s[nt][1] = __expf(fmaf(s[nt][1], scale, -mn0));
            s[nt][2] = __expf(fmaf(s[nt][2], scale, -mn1));
            s[nt][3] = __expf(fmaf(s[nt][3], scale, -mn1));
            sum0 += s[nt][0] + s[nt][1];
            sum1 += s[nt][2] + s[nt][3];
        }
        l0r = l0r * f0 + sum0;
        l1r = l1r * f1 + sum1;
#pragma unroll
        for (int nt2 = 0; nt2 < 6; nt2++) {
            oa[nt2][0] *= f0; oa[nt2][1] *= f0;
            oa[nt2][2] *= f1; oa[nt2][3] *= f1;
        }

        // ---- O += P V ----
#pragma unroll
        for (int t = 0; t < 4; t++) {
            uint32_t pa[4];
            pa[0] = pack_h2(s[2 * t][0],     s[2 * t][1]);
            pa[1] = pack_h2(s[2 * t][2],     s[2 * t][3]);
            pa[2] = pack_h2(s[2 * t + 1][0], s[2 * t + 1][1]);
            pa[3] = pack_h2(s[2 * t + 1][2], s[2 * t + 1][3]);
#pragma unroll
            for (int np = 0; np < 3; np++) {
                uint32_t r[4];
                ldmx4(r, cvta_s(Vc + (np * 16 + vb_r) * LDK + t * 16 + vb_c));
                mma16816(oa[2 * np],     pa, r[0], r[1]);
                mma16816(oa[2 * np + 1], pa, r[2], r[3]);
            }
        }
        __syncthreads();
    }

    // ---- epilogue: normalize, write fp16 [c][p] ----
    l0r += __shfl_xor_sync(0xffffffffu, l0r, 1);
    l0r += __shfl_xor_sync(0xffffffffu, l0r, 2);
    l1r += __shfl_xor_sync(0xffffffffu, l1r, 1);
    l1r += __shfl_xor_sync(0xffffffffu, l1r, 2);
    const float inv0 = 1.f / l0r, inv1 = 1.f / l1r;

    const int g = lane >> 2, tig = lane & 3;
    const int q_r = q0g + warp * 16 + g;
#pragma unroll
    for (int nt2 = 0; nt2 < 6; nt2++) {
        const int d = nt2 * 8 + 2 * tig;
        __half* dst = g_ao_h + ((size_t)bh * HD + d) * SEQ;
        dst[q_r]           = __float2half(oa[nt2][0] * inv0);
        dst[SEQ + q_r]     = __float2half(oa[nt2][1] * inv0);
        dst[q_r + 8]       = __float2half(oa[nt2][2] * inv1);
        dst[SEQ + q_r + 8] = __float2half(oa[nt2][3] * inv1);
    }
}

// ---------------------------------------------------------------------------
extern "C" void kernel_launch(void* const* d_in, const int* in_sizes, int n_in,
                              void* d_out, int out_size)
{
    const float* x      = (const float*)d_in[0];   // [8,384,32,32]
    const float* w_qkv  = (const float*)d_in[1];   // [1152,384]
    const float* w_proj = (const float*)d_in[2];   // [384,384]
    const float* b_proj = (const float*)d_in[3];   // [384]
    float* out = (float*)d_out;                    // [8,384,32,32]

    cvt_kernel<<<(N4_ALL + 255) / 256, 256>>>(x, w_qkv, w_proj);
    gemm_h_kernel<O3, 0><<<dim3(SEQ / 128, O3 / 128, BATCH), 256>>>(nullptr, nullptr);
    attn_h_kernel<<<dim3(SEQ / 128, BATCH * NH), 256>>>();
    gemm_h_kernel<CH, 1><<<dim3(SEQ / 128, CH / 128, BATCH), 256>>>(b_proj, out);
}

// round 5
// speedup vs baseline: 9.1367x; 1.0421x over previous
#include <cuda_runtime.h>
#include <cuda_fp16.h>
#include <cstdint>

#define BATCH 8
#define CH    384
#define NH    8
#define HD    48
#define SEQ   1024
#define O3    1152   // 3*CH

// fp16 scratch (device globals — allocation-free per harness rules)
__device__ __align__(16) __half g_x_h    [(size_t)BATCH * CH * SEQ];
__device__ __align__(16) __half g_wqkv_h [(size_t)O3 * CH];
__device__ __align__(16) __half g_wproj_h[(size_t)CH * CH];
__device__ __align__(16) __half g_qkv_h  [(size_t)BATCH * O3 * SEQ];
__device__ __align__(16) __half g_ao_h   [(size_t)BATCH * CH * SEQ];

// ---------------------------------------------------------------------------
// PTX helpers
// ---------------------------------------------------------------------------
__device__ __forceinline__ uint32_t cvta_s(const void* p) {
    return (uint32_t)__cvta_generic_to_shared(p);
}
__device__ __forceinline__ void ldmx4(uint32_t* r, uint32_t a) {
    asm volatile("ldmatrix.sync.aligned.m8n8.x4.shared.b16 {%0,%1,%2,%3},[%4];"
        : "=r"(r[0]), "=r"(r[1]), "=r"(r[2]), "=r"(r[3]) : "r"(a));
}
__device__ __forceinline__ void ldmx4t(uint32_t* r, uint32_t a) {
    asm volatile("ldmatrix.sync.aligned.m8n8.x4.trans.shared.b16 {%0,%1,%2,%3},[%4];"
        : "=r"(r[0]), "=r"(r[1]), "=r"(r[2]), "=r"(r[3]) : "r"(a));
}
__device__ __forceinline__ void mma16816(float* c, const uint32_t* a,
                                         uint32_t b0, uint32_t b1) {
    asm volatile(
        "mma.sync.aligned.m16n8k16.row.col.f32.f16.f16.f32 "
        "{%0,%1,%2,%3},{%4,%5,%6,%7},{%8,%9},{%0,%1,%2,%3};"
        : "+f"(c[0]), "+f"(c[1]), "+f"(c[2]), "+f"(c[3])
        : "r"(a[0]), "r"(a[1]), "r"(a[2]), "r"(a[3]), "r"(b0), "r"(b1));
}
__device__ __forceinline__ uint32_t pack_h2(float lo, float hi) {
    __half2 h = __floats2half2_rn(lo, hi);
    return *reinterpret_cast<uint32_t*>(&h);
}
__device__ __forceinline__ void cp16(uint32_t s, const void* g) {
    asm volatile("cp.async.cg.shared.global [%0], [%1], 16;" :: "r"(s), "l"(g));
}
__device__ __forceinline__ void cp_commit() { asm volatile("cp.async.commit_group;"); }
__device__ __forceinline__ void cp_wait1()  { asm volatile("cp.async.wait_group 1;"); }
__device__ __forceinline__ void cp_wait0()  { asm volatile("cp.async.wait_group 0;"); }

// ---------------------------------------------------------------------------
// fp32 -> fp16 pre-conversion of x, w_qkv, w_proj
// ---------------------------------------------------------------------------
#define N4_X  (BATCH * CH * SEQ / 4)
#define N4_WQ (O3 * CH / 4)
#define N4_WP (CH * CH / 4)
#define N4_ALL (N4_X + N4_WQ + N4_WP)

__global__ __launch_bounds__(256)
void cvt_kernel(const float* __restrict__ x,
                const float* __restrict__ wq,
                const float* __restrict__ wp)
{
    int i = blockIdx.x * 256 + threadIdx.x;
    if (i >= N4_ALL) return;
    const float4* src;
    __half* dst;
    int off;
    if (i < N4_X)              { src = (const float4*)x;  dst = g_x_h;     off = i; }
    else if (i < N4_X + N4_WQ) { src = (const float4*)wq; dst = g_wqkv_h;  off = i - N4_X; }
    else                       { src = (const float4*)wp; dst = g_wproj_h; off = i - N4_X - N4_WQ; }
    float4 v = src[off];
    *reinterpret_cast<uint2*>(dst + 4 * (size_t)off) =
        make_uint2(pack_h2(v.x, v.y), pack_h2(v.z, v.w));
}

// ---------------------------------------------------------------------------
// fp16 GEMM, 3-stage cp.async, 1 sync/iter.
// BM=128 BN=64 BK=32, 256 threads (8 warps 4x2), warp tile 32x32.
// ---------------------------------------------------------------------------
template<int M_CH, int IS_PROJ>
__global__ __launch_bounds__(256)
void gemm_h_kernel(const float* __restrict__ bias, float* __restrict__ Out32)
{
    constexpr int BM = 128, BN = 64, BK = 32;
    constexpr int LDA = BK + 8;   // 40
    constexpr int LDB = BN + 8;   // 72
    constexpr int NIT = CH / BK;  // 12

    __shared__ __align__(16) __half As[3][BM * LDA];
    __shared__ __align__(16) __half Bs[3][BK * LDB];

    const __half* gA = IS_PROJ ? g_wproj_h : g_wqkv_h;
    const __half* gB = (IS_PROJ ? g_ao_h : g_x_h) + (size_t)blockIdx.z * CH * SEQ;

    const int b   = blockIdx.z;
    const int o0  = blockIdx.y * BM;
    const int p0  = blockIdx.x * BN;
    const int tid = threadIdx.x;
    const int warp = tid >> 5, lane = tid & 31;
    const int wm = warp >> 1, wn = warp & 1;

    const int ar = tid >> 2, ac = (tid & 3) * 8;   // A: rows ar, ar+64
    const int br = tid >> 3, bc = (tid & 7) * 8;   // B: row br, chunk bc

    const int a_r = lane & 15;
    const int a_c = 8 * (lane >> 4);
    const int b_r = (lane & 7) + 8 * ((lane >> 3) & 1);
    const int b_c = 8 * (lane >> 4);

    float acc[2][4][4] = {};

    auto load_stage = [&](int st, int k0) {
        cp16(cvta_s(&As[st][ar * LDA + ac]),        gA + (size_t)(o0 + ar) * CH + k0 + ac);
        cp16(cvta_s(&As[st][(ar + 64) * LDA + ac]), gA + (size_t)(o0 + ar + 64) * CH + k0 + ac);
        cp16(cvta_s(&Bs[st][br * LDB + bc]), gB + (size_t)(k0 + br) * SEQ + p0 + bc);
        cp_commit();
    };

    load_stage(0, 0);
    load_stage(1, BK);

    for (int it = 0; it < NIT; it++) {
        if (it == NIT - 1) cp_wait0(); else cp_wait1();
        __syncthreads();
        if (it + 2 < NIT) load_stage((it + 2) % 3, (it + 2) * BK);

        const __half* Ac = As[it % 3];
        const __half* Bc = Bs[it % 3];
#pragma unroll
        for (int kk = 0; kk < BK; kk += 16) {
            uint32_t af[2][4];
#pragma unroll
            for (int mt = 0; mt < 2; mt++)
                ldmx4(af[mt], cvta_s(Ac + (wm * 32 + mt * 16 + a_r) * LDA + kk + a_c));
            uint32_t bf[4][2];
#pragma unroll
            for (int ntp = 0; ntp < 2; ntp++) {
                uint32_t r[4];
                ldmx4t(r, cvta_s(Bc + (kk + b_r) * LDB + wn * 32 + ntp * 16 + b_c));
                bf[2 * ntp][0] = r[0]; bf[2 * ntp][1] = r[1];
                bf[2 * ntp + 1][0] = r[2]; bf[2 * ntp + 1][1] = r[3];
            }
#pragma unroll
            for (int mt = 0; mt < 2; mt++)
#pragma unroll
                for (int nt = 0; nt < 4; nt++)
                    mma16816(acc[mt][nt], af[mt], bf[nt][0], bf[nt][1]);
        }
    }

    // ---- epilogue ----
    const int g = lane >> 2, tig = lane & 3;
#pragma unroll
    for (int mt = 0; mt < 2; mt++) {
        const int o_r = o0 + wm * 32 + mt * 16 + g;
#pragma unroll
        for (int nt = 0; nt < 4; nt++) {
            const int p_c = p0 + wn * 32 + nt * 8 + 2 * tig;
            if (!IS_PROJ) {
                __half* dst = g_qkv_h + ((size_t)b * O3 + o_r) * SEQ + p_c;
                *reinterpret_cast<uint32_t*>(dst) =
                    pack_h2(acc[mt][nt][0], acc[mt][nt][1]);
                *reinterpret_cast<uint32_t*>(dst + 8 * SEQ) =
                    pack_h2(acc[mt][nt][2], acc[mt][nt][3]);
            } else {
                const float bv0 = bias[o_r], bv1 = bias[o_r + 8];
                float* dst = Out32 + ((size_t)b * M_CH + o_r) * SEQ + p_c;
                *reinterpret_cast<float2*>(dst) =
                    make_float2(acc[mt][nt][0] + bv0, acc[mt][nt][1] + bv0);
                *reinterpret_cast<float2*>(dst + 8 * SEQ) =
                    make_float2(acc[mt][nt][2] + bv1, acc[mt][nt][3] + bv1);
            }
        }
    }
}

// ---------------------------------------------------------------------------
// Flash attention, 3-stage cp.async K/V ring (dynamic smem), 1 sync/iter.
// Per CTA: one (b,h), 128 queries (8 warps x 16 rows), key tiles of 64.
// ---------------------------------------------------------------------------
#define LDQ 136
#define LDK 72
#define ATTN_SMEM (HD * LDQ * 2 + 6 * HD * LDK * 2)   // 13056 + 41472 = 54528 B

__global__ __launch_bounds__(256)
void attn_h_kernel()
{
    constexpr int NJT = SEQ / 64;   // 16
    constexpr int KVST = HD * LDK;  // halves per K/V stage

    extern __shared__ __align__(16) __half dsm[];
    __half* Qs = dsm;
    __half* Ksb = dsm + HD * LDQ;
    __half* Vsb = Ksb + 3 * KVST;

    const int bh = blockIdx.y, qb = blockIdx.x;
    const int tid = threadIdx.x, warp = tid >> 5, lane = tid & 31;
    const int b = bh >> 3, h = bh & 7;

    const __half* qbase = g_qkv_h + ((size_t)b * O3 + h * HD) * SEQ;
    const __half* kbase = qbase + (size_t)CH * SEQ;
    const __half* vbase = qbase + (size_t)2 * CH * SEQ;
    const int q0g = qb * 128;

    const float scale = 0.14433756729740643f;   // 48^-0.5

    auto load_kv = [&](int st, int j0) {
#pragma unroll
        for (int rep = 0; rep < 3; rep++) {
            int i = tid + 256 * rep;
            if (i < HD * 8) {
                int d = i >> 3, c = (i & 7) * 8;
                cp16(cvta_s(Ksb + st * KVST + d * LDK + c), kbase + (size_t)d * SEQ + j0 + c);
            } else {
                int i2 = i - HD * 8;
                int d = i2 >> 3, c = (i2 & 7) * 8;
                cp16(cvta_s(Vsb + st * KVST + d * LDK + c), vbase + (size_t)d * SEQ + j0 + c);
            }
        }
        cp_commit();
    };

    load_kv(0, 0);
    load_kv(1, 64);

    // ---- Q tile [48][128] ----
    for (int i = tid; i < HD * 16; i += 256) {
        int d = i >> 4, c = (i & 15) * 8;
        *reinterpret_cast<uint4*>(Qs + d * LDQ + c) =
            *reinterpret_cast<const uint4*>(qbase + (size_t)d * SEQ + q0g + c);
    }
    __syncthreads();

    uint32_t qa[3][4];
    {
        const int r_off = (lane & 7) + 8 * (lane >> 4);
        const int c_off = warp * 16 + 8 * ((lane >> 3) & 1);
#pragma unroll
        for (int kt = 0; kt < 3; kt++)
            ldmx4t(qa[kt], cvta_s(Qs + (kt * 16 + r_off) * LDQ + c_off));
    }

    float m0r = -1e30f, m1r = -1e30f;
    float l0r = 0.f, l1r = 0.f;
    float oa[6][4] = {};

    const int kb_r = (lane & 7) + 8 * ((lane >> 3) & 1);
    const int kb_c = 8 * (lane >> 4);
    const int vb_r = (lane & 7) + 8 * (lane >> 4);
    const int vb_c = 8 * ((lane >> 3) & 1);

    for (int it = 0; it < NJT; it++) {
        if (it == NJT - 1) cp_wait0(); else cp_wait1();
        __syncthreads();
        if (it + 2 < NJT) load_kv((it + 2) % 3, (it + 2) * 64);

        const __half* Kc = Ksb + (it % 3) * KVST;
        const __half* Vc = Vsb + (it % 3) * KVST;

        // ---- S = Q K^T ----
        float s[8][4] = {};
#pragma unroll
        for (int kt = 0; kt < 3; kt++) {
            uint32_t bf[8][2];
#pragma unroll
            for (int ntp = 0; ntp < 4; ntp++) {
                uint32_t r[4];
                ldmx4t(r, cvta_s(Kc + (kt * 16 + kb_r) * LDK + ntp * 16 + kb_c));
                bf[2 * ntp][0] = r[0]; bf[2 * ntp][1] = r[1];
                bf[2 * ntp + 1][0] = r[2]; bf[2 * ntp + 1][1] = r[3];
            }
#pragma unroll
            for (int nt = 0; nt < 8; nt++)
                mma16816(s[nt], qa[kt], bf[nt][0], bf[nt][1]);
        }

        // ---- online softmax ----
        float mx0 = -1e30f, mx1 = -1e30f;
#pragma unroll
        for (int nt = 0; nt < 8; nt++) {
            mx0 = fmaxf(mx0, fmaxf(s[nt][0], s[nt][1]));
            mx1 = fmaxf(mx1, fmaxf(s[nt][2], s[nt][3]));
        }
        mx0 = fmaxf(mx0, __shfl_xor_sync(0xffffffffu, mx0, 1));
        mx0 = fmaxf(mx0, __shfl_xor_sync(0xffffffffu, mx0, 2));
        mx1 = fmaxf(mx1, __shfl_xor_sync(0xffffffffu, mx1, 1));
        mx1 = fmaxf(mx1, __shfl_xor_sync(0xffffffffu, mx1, 2));

        const float mn0 = fmaxf(m0r, mx0 * scale);
        const float mn1 = fmaxf(m1r, mx1 * scale);
        const float f0 = __expf(m0r - mn0);
        const float f1 = __expf(m1r - mn1);
        m0r = mn0; m1r = mn1;

        float sum0 = 0.f, sum1 = 0.f;
#pragma unroll
        for (int nt = 0; nt < 8; nt++) {
            s[nt][0] = __expf(fmaf(s[nt][0], scale, -mn0));
            s[nt][1] = __expf(fmaf(s[nt][1], scale, -mn0));
            s[nt][2] = __expf(fmaf(s[nt][2], scale, -mn1));
            s[nt][3] = __expf(fmaf(s[nt][3], scale, -mn1));
            sum0 += s[nt][0] + s[nt][1];
            sum1 += s[nt][2] + s[nt][3];
        }
        l0r = l0r * f0 + sum0;
        l1r = l1r * f1 + sum1;
#pragma unroll
        for (int nt2 = 0; nt2 < 6; nt2++) {
            oa[nt2][0] *= f0; oa[nt2][1] *= f0;
            oa[nt2][2] *= f1; oa[nt2][3] *= f1;
        }

        // ---- O += P V ----
#pragma unroll
        for (int t = 0; t < 4; t++) {
            uint32_t pa[4];
            pa[0] = pack_h2(s[2 * t][0],     s[2 * t][1]);
            pa[1] = pack_h2(s[2 * t][2],     s[2 * t][3]);
            pa[2] = pack_h2(s[2 * t + 1][0], s[2 * t + 1][1]);
            pa[3] = pack_h2(s[2 * t + 1][2], s[2 * t + 1][3]);
#pragma unroll
            for (int np = 0; np < 3; np++) {
                uint32_t r[4];
                ldmx4(r, cvta_s(Vc + (np * 16 + vb_r) * LDK + t * 16 + vb_c));
                mma16816(oa[2 * np],     pa, r[0], r[1]);
                mma16816(oa[2 * np + 1], pa, r[2], r[3]);
            }
        }
    }

    // ---- epilogue ----
    l0r += __shfl_xor_sync(0xffffffffu, l0r, 1);
    l0r += __shfl_xor_sync(0xffffffffu, l0r, 2);
    l1r += __shfl_xor_sync(0xffffffffu, l1r, 1);
    l1r += __shfl_xor_sync(0xffffffffu, l1r, 2);
    const float inv0 = 1.f / l0r, inv1 = 1.f / l1r;

    const int g = lane >> 2, tig = lane & 3;
    const int q_r = q0g + warp * 16 + g;
#pragma unroll
    for (int nt2 = 0; nt2 < 6; nt2++) {
        const int d = nt2 * 8 + 2 * tig;
        __half* dst = g_ao_h + ((size_t)bh * HD + d) * SEQ;
        dst[q_r]           = __float2half(oa[nt2][0] * inv0);
        dst[SEQ + q_r]     = __float2half(oa[nt2][1] * inv0);
        dst[q_r + 8]       = __float2half(oa[nt2][2] * inv1);
        dst[SEQ + q_r + 8] = __float2half(oa[nt2][3] * inv1);
    }
}

// ---------------------------------------------------------------------------
extern "C" void kernel_launch(void* const* d_in, const int* in_sizes, int n_in,
                              void* d_out, int out_size)
{
    const float* x      = (const float*)d_in[0];
    const float* w_qkv  = (const float*)d_in[1];
    const float* w_proj = (const float*)d_in[2];
    const float* b_proj = (const float*)d_in[3];
    float* out = (float*)d_out;

    static bool attr_set = false;
    if (!attr_set) {
        cudaFuncSetAttribute(attn_h_kernel,
                             cudaFuncAttributeMaxDynamicSharedMemorySize, ATTN_SMEM);
        attr_set = true;
    }

    cvt_kernel<<<(N4_ALL + 255) / 256, 256>>>(x, w_qkv, w_proj);
    gemm_h_kernel<O3, 0><<<dim3(SEQ / 64, O3 / 128, BATCH), 256>>>(nullptr, nullptr);
    attn_h_kernel<<<dim3(SEQ / 128, BATCH * NH), 256, ATTN_SMEM>>>();
    gemm_h_kernel<CH, 1><<<dim3(SEQ / 64, CH / 128, BATCH), 256>>>(b_proj, out);
}

// round 7
// speedup vs baseline: 9.1730x; 1.0040x over previous
#include <cuda_runtime.h>
#include <cuda_fp16.h>
#include <cstdint>

#define BATCH 8
#define CH    384
#define NH    8
#define HD    48
#define SEQ   1024
#define O3    1152   // 3*CH

// fp16 scratch (device globals — allocation-free per harness rules)
__device__ __align__(16) __half g_x_h    [(size_t)BATCH * CH * SEQ];
__device__ __align__(16) __half g_wqkv_h [(size_t)O3 * CH];
__device__ __align__(16) __half g_wproj_h[(size_t)CH * CH];
__device__ __align__(16) __half g_qkv_h  [(size_t)BATCH * O3 * SEQ];
__device__ __align__(16) __half g_ao_h   [(size_t)BATCH * CH * SEQ];

// ---------------------------------------------------------------------------
// PTX helpers
// ---------------------------------------------------------------------------
__device__ __forceinline__ uint32_t cvta_s(const void* p) {
    return (uint32_t)__cvta_generic_to_shared(p);
}
__device__ __forceinline__ void ldmx4(uint32_t* r, uint32_t a) {
    asm volatile("ldmatrix.sync.aligned.m8n8.x4.shared.b16 {%0,%1,%2,%3},[%4];"
        : "=r"(r[0]), "=r"(r[1]), "=r"(r[2]), "=r"(r[3]) : "r"(a));
}
__device__ __forceinline__ void ldmx4t(uint32_t* r, uint32_t a) {
    asm volatile("ldmatrix.sync.aligned.m8n8.x4.trans.shared.b16 {%0,%1,%2,%3},[%4];"
        : "=r"(r[0]), "=r"(r[1]), "=r"(r[2]), "=r"(r[3]) : "r"(a));
}
__device__ __forceinline__ void mma16816(float* c, const uint32_t* a,
                                         uint32_t b0, uint32_t b1) {
    asm volatile(
        "mma.sync.aligned.m16n8k16.row.col.f32.f16.f16.f32 "
        "{%0,%1,%2,%3},{%4,%5,%6,%7},{%8,%9},{%0,%1,%2,%3};"
        : "+f"(c[0]), "+f"(c[1]), "+f"(c[2]), "+f"(c[3])
        : "r"(a[0]), "r"(a[1]), "r"(a[2]), "r"(a[3]), "r"(b0), "r"(b1));
}
__device__ __forceinline__ uint32_t pack_h2(float lo, float hi) {
    __half2 h = __floats2half2_rn(lo, hi);
    return *reinterpret_cast<uint32_t*>(&h);
}
__device__ __forceinline__ void cp16(uint32_t s, const void* g) {
    asm volatile("cp.async.cg.shared.global [%0], [%1], 16;" :: "r"(s), "l"(g));
}
__device__ __forceinline__ void cp_commit() { asm volatile("cp.async.commit_group;"); }
__device__ __forceinline__ void cp_wait1()  { asm volatile("cp.async.wait_group 1;"); }
__device__ __forceinline__ void cp_wait0()  { asm volatile("cp.async.wait_group 0;"); }

// ---------------------------------------------------------------------------
// fp32 -> fp16 pre-conversion of x, w_qkv, w_proj (identical to R4)
// ---------------------------------------------------------------------------
#define N4_X  (BATCH * CH * SEQ / 4)
#define N4_WQ (O3 * CH / 4)
#define N4_WP (CH * CH / 4)
#define N4_ALL (N4_X + N4_WQ + N4_WP)

__global__ __launch_bounds__(256)
void cvt_kernel(const float* __restrict__ x,
                const float* __restrict__ wq,
                const float* __restrict__ wp)
{
    int i = blockIdx.x * 256 + threadIdx.x;
    if (i >= N4_ALL) return;
    const float4* src;
    __half* dst;
    int off;
    if (i < N4_X)              { src = (const float4*)x;  dst = g_x_h;     off = i; }
    else if (i < N4_X + N4_WQ) { src = (const float4*)wq; dst = g_wqkv_h;  off = i - N4_X; }
    else                       { src = (const float4*)wp; dst = g_wproj_h; off = i - N4_X - N4_WQ; }
    float4 v = src[off];
    *reinterpret_cast<uint2*>(dst + 4 * (size_t)off) =
        make_uint2(pack_h2(v.x, v.y), pack_h2(v.z, v.w));
}

// ---------------------------------------------------------------------------
// fp16 GEMM, BK=64, 3-stage cp.async ring (dynamic smem), 1 sync per 64-k.
// IS_PROJ=0: BM=128, 256 thr (8 warps 4x2).  IS_PROJ=1: BM=64, 128 thr (2x2).
// Warp tile 32x32, BN=64.
// ---------------------------------------------------------------------------
#define GEMM_LD 72   // 64 + 8 halves row stride (A and B tiles)

template<int IS_PROJ>
__global__ __launch_bounds__(IS_PROJ ? 128 : 256)
void gemm_h_kernel(const float* __restrict__ bias, float* __restrict__ Out32)
{
    constexpr int BM = IS_PROJ ? 64 : 128;
    constexpr int T  = IS_PROJ ? 128 : 256;
    constexpr int BK = 64, BN = 64;
    constexpr int LD = GEMM_LD;
    constexpr int A_H = BM * LD;          // halves per A stage
    constexpr int B_H = BK * LD;          // halves per B stage
    constexpr int ST_H = A_H + B_H;
    constexpr int NIT = CH / BK;          // 6
    constexpr int M_CH = IS_PROJ ? CH : O3;

    extern __shared__ __align__(16) __half gsm[];

    const __half* gA = IS_PROJ ? g_wproj_h : g_wqkv_h;
    const __half* gB = (IS_PROJ ? g_ao_h : g_x_h) + (size_t)blockIdx.z * CH * SEQ;

    const int b   = blockIdx.z;
    const int o0  = blockIdx.y * BM;
    const int p0  = blockIdx.x * BN;
    const int tid = threadIdx.x;
    const int warp = tid >> 5, lane = tid & 31;
    const int wm = warp >> 1, wn = warp & 1;

    const int a_r = lane & 15;
    const int a_c = 8 * (lane >> 4);
    const int b_r = (lane & 7) + 8 * ((lane >> 3) & 1);
    const int b_c = 8 * (lane >> 4);

    float acc[2][4][4] = {};

    auto load_stage = [&](int st, int k0) {
        __half* S = gsm + st * ST_H;
#pragma unroll
        for (int j = 0; j < 4; j++) {                 // A: BM*8 chunks
            int i = tid + T * j;
            int row = i >> 3, c8 = i & 7;
            cp16(cvta_s(S + row * LD + c8 * 8),
                 gA + (size_t)(o0 + row) * CH + k0 + c8 * 8);
        }
#pragma unroll
        for (int j = 0; j < (IS_PROJ ? 4 : 2); j++) { // B: 512 chunks
            int i = tid + T * j;
            int row = i >> 3, c8 = i & 7;
            cp16(cvta_s(S + A_H + row * LD + c8 * 8),
                 gB + (size_t)(k0 + row) * SEQ + p0 + c8 * 8);
        }
        cp_commit();
    };

    load_stage(0, 0);
    load_stage(1, BK);

    for (int it = 0; it < NIT; it++) {
        if (it == NIT - 1) cp_wait0(); else cp_wait1();
        __syncthreads();
        if (it + 2 < NIT) load_stage((it + 2) % 3, (it + 2) * BK);

        const __half* Ac = gsm + (it % 3) * ST_H;
        const __half* Bc = Ac + A_H;
#pragma unroll
        for (int kk = 0; kk < BK; kk += 16) {
            uint32_t af[2][4];
#pragma unroll
            for (int mt = 0; mt < 2; mt++)
                ldmx4(af[mt], cvta_s(Ac + (wm * 32 + mt * 16 + a_r) * LD + kk + a_c));
            uint32_t bf[4][2];
#pragma unroll
            for (int ntp = 0; ntp < 2; ntp++) {
                uint32_t r[4];
                ldmx4t(r, cvta_s(Bc + (kk + b_r) * LD + wn * 32 + ntp * 16 + b_c));
                bf[2 * ntp][0] = r[0]; bf[2 * ntp][1] = r[1];
                bf[2 * ntp + 1][0] = r[2]; bf[2 * ntp + 1][1] = r[3];
            }
#pragma unroll
            for (int mt = 0; mt < 2; mt++)
#pragma unroll
                for (int nt = 0; nt < 4; nt++)
                    mma16816(acc[mt][nt], af[mt], bf[nt][0], bf[nt][1]);
        }
    }

    // ---- epilogue ----
    const int g = lane >> 2, tig = lane & 3;
#pragma unroll
    for (int mt = 0; mt < 2; mt++) {
        const int o_r = o0 + wm * 32 + mt * 16 + g;
#pragma unroll
        for (int nt = 0; nt < 4; nt++) {
            const int p_c = p0 + wn * 32 + nt * 8 + 2 * tig;
            if (!IS_PROJ) {
                __half* dst = g_qkv_h + ((size_t)b * M_CH + o_r) * SEQ + p_c;
                *reinterpret_cast<uint32_t*>(dst) =
                    pack_h2(acc[mt][nt][0], acc[mt][nt][1]);
                *reinterpret_cast<uint32_t*>(dst + 8 * SEQ) =
                    pack_h2(acc[mt][nt][2], acc[mt][nt][3]);
            } else {
                const float bv0 = bias[o_r], bv1 = bias[o_r + 8];
                float* dst = Out32 + ((size_t)b * M_CH + o_r) * SEQ + p_c;
                *reinterpret_cast<float2*>(dst) =
                    make_float2(acc[mt][nt][0] + bv0, acc[mt][nt][1] + bv0);
                *reinterpret_cast<float2*>(dst + 8 * SEQ) =
                    make_float2(acc[mt][nt][2] + bv1, acc[mt][nt][3] + bv1);
            }
        }
    }
}

#define QKV_SMEM  (3 * (128 * GEMM_LD + 64 * GEMM_LD) * 2)   // 82944 B
#define PROJ_SMEM (3 * (64 * GEMM_LD + 64 * GEMM_LD) * 2)    // 55296 B

// ---------------------------------------------------------------------------
// Flash attention (identical to R4): 3-stage cp.async K/V ring, 1 sync/iter.
// Per CTA: one (b,h), 128 queries (8 warps x 16 rows), key tiles of 64.
// ---------------------------------------------------------------------------
#define LDQ 136
#define LDK 72
#define ATTN_SMEM (HD * LDQ * 2 + 6 * HD * LDK * 2)   // 54528 B

__global__ __launch_bounds__(256)
void attn_h_kernel()
{
    constexpr int NJT = SEQ / 64;
    constexpr int KVST = HD * LDK;

    extern __shared__ __align__(16) __half dsm[];
    __half* Qs = dsm;
    __half* Ksb = dsm + HD * LDQ;
    __half* Vsb = Ksb + 3 * KVST;

    const int bh = blockIdx.y, qb = blockIdx.x;
    const int tid = threadIdx.x, warp = tid >> 5, lane = tid & 31;
    const int b = bh >> 3, h = bh & 7;

    const __half* qbase = g_qkv_h + ((size_t)b * O3 + h * HD) * SEQ;
    const __half* kbase = qbase + (size_t)CH * SEQ;
    const __half* vbase = qbase + (size_t)2 * CH * SEQ;
    const int q0g = qb * 128;

    const float scale = 0.14433756729740643f;

    auto load_kv = [&](int st, int j0) {
#pragma unroll
        for (int rep = 0; rep < 3; rep++) {
            int i = tid + 256 * rep;
            if (i < HD * 8) {
                int d = i >> 3, c = (i & 7) * 8;
                cp16(cvta_s(Ksb + st * KVST + d * LDK + c), kbase + (size_t)d * SEQ + j0 + c);
            } else {
                int i2 = i - HD * 8;
                int d = i2 >> 3, c = (i2 & 7) * 8;
                cp16(cvta_s(Vsb + st * KVST + d * LDK + c), vbase + (size_t)d * SEQ + j0 + c);
            }
        }
        cp_commit();
    };

    load_kv(0, 0);
    load_kv(1, 64);

    for (int i = tid; i < HD * 16; i += 256) {
        int d = i >> 4, c = (i & 15) * 8;
        *reinterpret_cast<uint4*>(Qs + d * LDQ + c) =
            *reinterpret_cast<const uint4*>(qbase + (size_t)d * SEQ + q0g + c);
    }
    __syncthreads();

    uint32_t qa[3][4];
    {
        const int r_off = (lane & 7) + 8 * (lane >> 4);
        const int c_off = warp * 16 + 8 * ((lane >> 3) & 1);
#pragma unroll
        for (int kt = 0; kt < 3; kt++)
            ldmx4t(qa[kt], cvta_s(Qs + (kt * 16 + r_off) * LDQ + c_off));
    }

    float m0r = -1e30f, m1r = -1e30f;
    float l0r = 0.f, l1r = 0.f;
    float oa[6][4] = {};

    const int kb_r = (lane & 7) + 8 * ((lane >> 3) & 1);
    const int kb_c = 8 * (lane >> 4);
    const int vb_r = (lane & 7) + 8 * (lane >> 4);
    const int vb_c = 8 * ((lane >> 3) & 1);

    for (int it = 0; it < NJT; it++) {
        if (it == NJT - 1) cp_wait0(); else cp_wait1();
        __syncthreads();
        if (it + 2 < NJT) load_kv((it + 2) % 3, (it + 2) * 64);

        const __half* Kc = Ksb + (it % 3) * KVST;
        const __half* Vc = Vsb + (it % 3) * KVST;

        float s[8][4] = {};
#pragma unroll
        for (int kt = 0; kt < 3; kt++) {
            uint32_t bf[8][2];
#pragma unroll
            for (int ntp = 0; ntp < 4; ntp++) {
                uint32_t r[4];
                ldmx4t(r, cvta_s(Kc + (kt * 16 + kb_r) * LDK + ntp * 16 + kb_c));
                bf[2 * ntp][0] = r[0]; bf[2 * ntp][1] = r[1];
                bf[2 * ntp + 1][0] = r[2]; bf[2 * ntp + 1][1] = r[3];
            }
#pragma unroll
            for (int nt = 0; nt < 8; nt++)
                mma16816(s[nt], qa[kt], bf[nt][0], bf[nt][1]);
        }

        float mx0 = -1e30f, mx1 = -1e30f;
#pragma unroll
        for (int nt = 0; nt < 8; nt++) {
            mx0 = fmaxf(mx0, fmaxf(s[nt][0], s[nt][1]));
            mx1 = fmaxf(mx1, fmaxf(s[nt][2], s[nt][3]));
        }
        mx0 = fmaxf(mx0, __shfl_xor_sync(0xffffffffu, mx0, 1));
        mx0 = fmaxf(mx0, __shfl_xor_sync(0xffffffffu, mx0, 2));
        mx1 = fmaxf(mx1, __shfl_xor_sync(0xffffffffu, mx1, 1));
        mx1 = fmaxf(mx1, __shfl_xor_sync(0xffffffffu, mx1, 2));

        const float mn0 = fmaxf(m0r, mx0 * scale);
        const float mn1 = fmaxf(m1r, mx1 * scale);
        const float f0 = __expf(m0r - mn0);
        const float f1 = __expf(m1r - mn1);
        m0r = mn0; m1r = mn1;

        float sum0 = 0.f, sum1 = 0.f;
#pragma unroll
        for (int nt = 0; nt < 8; nt++) {
            s[nt][0] = __expf(fmaf(s[nt][0], scale, -mn0));
            s[nt][1] = __expf(fmaf(s[nt][1], scale, -mn0));
            s[nt][2] = __expf(fmaf(s[nt][2], scale, -mn1));
            s[nt][3] = __expf(fmaf(s[nt][3], scale, -mn1));
            sum0 += s[nt][0] + s[nt][1];
            sum1 += s[nt][2] + s[nt][3];
        }
        l0r = l0r * f0 + sum0;
        l1r = l1r * f1 + sum1;
#pragma unroll
        for (int nt2 = 0; nt2 < 6; nt2++) {
            oa[nt2][0] *= f0; oa[nt2][1] *= f0;
            oa[nt2][2] *= f1; oa[nt2][3] *= f1;
        }

#pragma unroll
        for (int t = 0; t < 4; t++) {
            uint32_t pa[4];
            pa[0] = pack_h2(s[2 * t][0],     s[2 * t][1]);
            pa[1] = pack_h2(s[2 * t][2],     s[2 * t][3]);
            pa[2] = pack_h2(s[2 * t + 1][0], s[2 * t + 1][1]);
            pa[3] = pack_h2(s[2 * t + 1][2], s[2 * t + 1][3]);
#pragma unroll
            for (int np = 0; np < 3; np++) {
                uint32_t r[4];
                ldmx4(r, cvta_s(Vc + (np * 16 + vb_r) * LDK + t * 16 + vb_c));
                mma16816(oa[2 * np],     pa, r[0], r[1]);
                mma16816(oa[2 * np + 1], pa, r[2], r[3]);
            }
        }
    }

    l0r += __shfl_xor_sync(0xffffffffu, l0r, 1);
    l0r += __shfl_xor_sync(0xffffffffu, l0r, 2);
    l1r += __shfl_xor_sync(0xffffffffu, l1r, 1);
    l1r += __shfl_xor_sync(0xffffffffu, l1r, 2);
    const float inv0 = 1.f / l0r, inv1 = 1.f / l1r;

    const int g = lane >> 2, tig = lane & 3;
    const int q_r = q0g + warp * 16 + g;
#pragma unroll
    for (int nt2 = 0; nt2 < 6; nt2++) {
        const int d = nt2 * 8 + 2 * tig;
        __half* dst = g_ao_h + ((size_t)bh * HD + d) * SEQ;
        dst[q_r]           = __float2half(oa[nt2][0] * inv0);
        dst[SEQ + q_r]     = __float2half(oa[nt2][1] * inv0);
        dst[q_r + 8]       = __float2half(oa[nt2][2] * inv1);
        dst[SEQ + q_r + 8] = __float2half(oa[nt2][3] * inv1);
    }
}

// ---------------------------------------------------------------------------
extern "C" void kernel_launch(void* const* d_in, const int* in_sizes, int n_in,
                              void* d_out, int out_size)
{
    const float* x      = (const float*)d_in[0];
    const float* w_qkv  = (const float*)d_in[1];
    const float* w_proj = (const float*)d_in[2];
    const float* b_proj = (const float*)d_in[3];
    float* out = (float*)d_out;

    static bool attr_set = false;
    if (!attr_set) {
        cudaFuncSetAttribute(attn_h_kernel,
                             cudaFuncAttributeMaxDynamicSharedMemorySize, ATTN_SMEM);
        cudaFuncSetAttribute(gemm_h_kernel<0>,
                             cudaFuncAttributeMaxDynamicSharedMemorySize, QKV_SMEM);
        cudaFuncSetAttribute(gemm_h_kernel<1>,
                             cudaFuncAttributeMaxDynamicSharedMemorySize, PROJ_SMEM);
        attr_set = true;
    }

    cvt_kernel<<<(N4_ALL + 255) / 256, 256>>>(x, w_qkv, w_proj);
    gemm_h_kernel<0><<<dim3(SEQ / 64, O3 / 128, BATCH), 256, QKV_SMEM>>>(nullptr, nullptr);
    attn_h_kernel<<<dim3(SEQ / 128, BATCH * NH), 256, ATTN_SMEM>>>();
    gemm_h_kernel<1><<<dim3(SEQ / 64, CH / 64, BATCH), 128, PROJ_SMEM>>>(b_proj, out);
}

// round 8
// speedup vs baseline: 9.3041x; 1.0143x over previous
#include <cuda_runtime.h>
#include <cuda_fp16.h>
#include <cstdint>

#define BATCH 8
#define CH    384
#define NH    8
#define HD    48
#define SEQ   1024
#define O3    1152   // 3*CH

// fp16 scratch (device globals — allocation-free per harness rules)
__device__ __align__(16) __half g_x_h    [(size_t)BATCH * CH * SEQ];
__device__ __align__(16) __half g_wqkv_h [(size_t)O3 * CH];
__device__ __align__(16) __half g_wproj_h[(size_t)CH * CH];
__device__ __align__(16) __half g_qkv_h  [(size_t)BATCH * O3 * SEQ];
__device__ __align__(16) __half g_ao_h   [(size_t)BATCH * CH * SEQ];

// ---------------------------------------------------------------------------
// PTX helpers
// ---------------------------------------------------------------------------
__device__ __forceinline__ uint32_t cvta_s(const void* p) {
    return (uint32_t)__cvta_generic_to_shared(p);
}
__device__ __forceinline__ void ldmx4(uint32_t* r, uint32_t a) {
    asm volatile("ldmatrix.sync.aligned.m8n8.x4.shared.b16 {%0,%1,%2,%3},[%4];"
        : "=r"(r[0]), "=r"(r[1]), "=r"(r[2]), "=r"(r[3]) : "r"(a));
}
__device__ __forceinline__ void ldmx4t(uint32_t* r, uint32_t a) {
    asm volatile("ldmatrix.sync.aligned.m8n8.x4.trans.shared.b16 {%0,%1,%2,%3},[%4];"
        : "=r"(r[0]), "=r"(r[1]), "=r"(r[2]), "=r"(r[3]) : "r"(a));
}
__device__ __forceinline__ void mma16816(float* c, const uint32_t* a,
                                         uint32_t b0, uint32_t b1) {
    asm volatile(
        "mma.sync.aligned.m16n8k16.row.col.f32.f16.f16.f32 "
        "{%0,%1,%2,%3},{%4,%5,%6,%7},{%8,%9},{%0,%1,%2,%3};"
        : "+f"(c[0]), "+f"(c[1]), "+f"(c[2]), "+f"(c[3])
        : "r"(a[0]), "r"(a[1]), "r"(a[2]), "r"(a[3]), "r"(b0), "r"(b1));
}
__device__ __forceinline__ uint32_t pack_h2(float lo, float hi) {
    __half2 h = __floats2half2_rn(lo, hi);
    return *reinterpret_cast<uint32_t*>(&h);
}
__device__ __forceinline__ float ex2f(float x) {
    float y;
    asm("ex2.approx.f32 %0, %1;" : "=f"(y) : "f"(x));
    return y;
}
__device__ __forceinline__ void cp16(uint32_t s, const void* g) {
    asm volatile("cp.async.cg.shared.global [%0], [%1], 16;" :: "r"(s), "l"(g));
}
__device__ __forceinline__ void cp_commit() { asm volatile("cp.async.commit_group;"); }
__device__ __forceinline__ void cp_wait1()  { asm volatile("cp.async.wait_group 1;"); }
__device__ __forceinline__ void cp_wait0()  { asm volatile("cp.async.wait_group 0;"); }

// ---------------------------------------------------------------------------
// fp32 -> fp16 pre-conversion of x, w_qkv, w_proj
// ---------------------------------------------------------------------------
#define N4_X  (BATCH * CH * SEQ / 4)
#define N4_WQ (O3 * CH / 4)
#define N4_WP (CH * CH / 4)
#define N4_ALL (N4_X + N4_WQ + N4_WP)

__global__ __launch_bounds__(256)
void cvt_kernel(const float* __restrict__ x,
                const float* __restrict__ wq,
                const float* __restrict__ wp)
{
    int i = blockIdx.x * 256 + threadIdx.x;
    if (i >= N4_ALL) return;
    const float4* src;
    __half* dst;
    int off;
    if (i < N4_X)              { src = (const float4*)x;  dst = g_x_h;     off = i; }
    else if (i < N4_X + N4_WQ) { src = (const float4*)wq; dst = g_wqkv_h;  off = i - N4_X; }
    else                       { src = (const float4*)wp; dst = g_wproj_h; off = i - N4_X - N4_WQ; }
    float4 v = src[off];
    *reinterpret_cast<uint2*>(dst + 4 * (size_t)off) =
        make_uint2(pack_h2(v.x, v.y), pack_h2(v.z, v.w));
}

// ---------------------------------------------------------------------------
// fp16 GEMM, BK=64, 3-stage cp.async ring, fragment double-buffering:
// LDSM group for k-step i+1 issues before the HMMA burst of step i.
// IS_PROJ=0: BM=128, 256 thr.  IS_PROJ=1: BM=64, 128 thr.  Warp tile 32x32.
// ---------------------------------------------------------------------------
#define GEMM_LD 72   // 64 + 8 halves row stride

template<int IS_PROJ>
__global__ __launch_bounds__(IS_PROJ ? 128 : 256)
void gemm_h_kernel(const float* __restrict__ bias, float* __restrict__ Out32)
{
    constexpr int BM = IS_PROJ ? 64 : 128;
    constexpr int T  = IS_PROJ ? 128 : 256;
    constexpr int BK = 64, BN = 64;
    constexpr int LD = GEMM_LD;
    constexpr int A_H = BM * LD;
    constexpr int B_H = BK * LD;
    constexpr int ST_H = A_H + B_H;
    constexpr int NIT = CH / BK;          // 6
    constexpr int M_CH = IS_PROJ ? CH : O3;

    extern __shared__ __align__(16) __half gsm[];

    const __half* gA = IS_PROJ ? g_wproj_h : g_wqkv_h;
    const __half* gB = (IS_PROJ ? g_ao_h : g_x_h) + (size_t)blockIdx.z * CH * SEQ;

    const int b   = blockIdx.z;
    const int o0  = blockIdx.y * BM;
    const int p0  = blockIdx.x * BN;
    const int tid = threadIdx.x;
    const int warp = tid >> 5, lane = tid & 31;
    const int wm = warp >> 1, wn = warp & 1;

    const int a_r = lane & 15;
    const int a_c = 8 * (lane >> 4);
    const int b_r = (lane & 7) + 8 * ((lane >> 3) & 1);
    const int b_c = 8 * (lane >> 4);

    float acc[2][4][4] = {};

    auto load_stage = [&](int st, int k0) {
        __half* S = gsm + st * ST_H;
#pragma unroll
        for (int j = 0; j < 4; j++) {
            int i = tid + T * j;
            int row = i >> 3, c8 = i & 7;
            cp16(cvta_s(S + row * LD + c8 * 8),
                 gA + (size_t)(o0 + row) * CH + k0 + c8 * 8);
        }
#pragma unroll
        for (int j = 0; j < (IS_PROJ ? 4 : 2); j++) {
            int i = tid + T * j;
            int row = i >> 3, c8 = i & 7;
            cp16(cvta_s(S + A_H + row * LD + c8 * 8),
                 gB + (size_t)(k0 + row) * SEQ + p0 + c8 * 8);
        }
        cp_commit();
    };

    load_stage(0, 0);
    load_stage(1, BK);

    uint32_t af[2][2][4];   // [slot][mt][reg]
    uint32_t bf[2][4][2];   // [slot][nt][reg]

    for (int it = 0; it < NIT; it++) {
        if (it == NIT - 1) cp_wait0(); else cp_wait1();
        __syncthreads();
        if (it + 2 < NIT) load_stage((it + 2) % 3, (it + 2) * BK);

        const __half* Ac = gsm + (it % 3) * ST_H;
        const __half* Bc = Ac + A_H;

        auto ldfrag = [&](int slot, int kk) {
#pragma unroll
            for (int mt = 0; mt < 2; mt++)
                ldmx4(af[slot][mt],
                      cvta_s(Ac + (wm * 32 + mt * 16 + a_r) * LD + kk + a_c));
#pragma unroll
            for (int ntp = 0; ntp < 2; ntp++) {
                uint32_t r[4];
                ldmx4t(r, cvta_s(Bc + (kk + b_r) * LD + wn * 32 + ntp * 16 + b_c));
                bf[slot][2 * ntp][0] = r[0]; bf[slot][2 * ntp][1] = r[1];
                bf[slot][2 * ntp + 1][0] = r[2]; bf[slot][2 * ntp + 1][1] = r[3];
            }
        };

        ldfrag(0, 0);
#pragma unroll
        for (int ki = 0; ki < 4; ki++) {
            if (ki < 3) ldfrag((ki + 1) & 1, (ki + 1) * 16);   // prefetch next k-step
            const int c = ki & 1;
#pragma unroll
            for (int mt = 0; mt < 2; mt++)
#pragma unroll
                for (int nt = 0; nt < 4; nt++)
                    mma16816(acc[mt][nt], af[c][mt], bf[c][nt][0], bf[c][nt][1]);
        }
    }

    // ---- epilogue ----
    const int g = lane >> 2, tig = lane & 3;
#pragma unroll
    for (int mt = 0; mt < 2; mt++) {
        const int o_r = o0 + wm * 32 + mt * 16 + g;
#pragma unroll
        for (int nt = 0; nt < 4; nt++) {
            const int p_c = p0 + wn * 32 + nt * 8 + 2 * tig;
            if (!IS_PROJ) {
                __half* dst = g_qkv_h + ((size_t)b * M_CH + o_r) * SEQ + p_c;
                *reinterpret_cast<uint32_t*>(dst) =
                    pack_h2(acc[mt][nt][0], acc[mt][nt][1]);
                *reinterpret_cast<uint32_t*>(dst + 8 * SEQ) =
                    pack_h2(acc[mt][nt][2], acc[mt][nt][3]);
            } else {
                const float bv0 = bias[o_r], bv1 = bias[o_r + 8];
                float* dst = Out32 + ((size_t)b * M_CH + o_r) * SEQ + p_c;
                *reinterpret_cast<float2*>(dst) =
                    make_float2(acc[mt][nt][0] + bv0, acc[mt][nt][1] + bv0);
                *reinterpret_cast<float2*>(dst + 8 * SEQ) =
                    make_float2(acc[mt][nt][2] + bv1, acc[mt][nt][3] + bv1);
            }
        }
    }
}

#define QKV_SMEM  (3 * (128 * GEMM_LD + 64 * GEMM_LD) * 2)   // 82944 B
#define PROJ_SMEM (3 * (64 * GEMM_LD + 64 * GEMM_LD) * 2)    // 55296 B

// ---------------------------------------------------------------------------
// Flash attention: 3-stage cp.async K/V ring, softmax in log2 domain (ex2).
// Per CTA: one (b,h), 128 queries (8 warps x 16 rows), key tiles of 64.
// ---------------------------------------------------------------------------
#define LDQ 136
#define LDK 72
#define ATTN_SMEM (HD * LDQ * 2 + 6 * HD * LDK * 2)   // 54528 B

__global__ __launch_bounds__(256)
void attn_h_kernel()
{
    constexpr int NJT = SEQ / 64;
    constexpr int KVST = HD * LDK;

    extern __shared__ __align__(16) __half dsm[];
    __half* Qs = dsm;
    __half* Ksb = dsm + HD * LDQ;
    __half* Vsb = Ksb + 3 * KVST;

    const int bh = blockIdx.y, qb = blockIdx.x;
    const int tid = threadIdx.x, warp = tid >> 5, lane = tid & 31;
    const int b = bh >> 3, h = bh & 7;

    const __half* qbase = g_qkv_h + ((size_t)b * O3 + h * HD) * SEQ;
    const __half* kbase = qbase + (size_t)CH * SEQ;
    const __half* vbase = qbase + (size_t)2 * CH * SEQ;
    const int q0g = qb * 128;

    // 48^-0.5 * log2(e): softmax runs in log2 domain, ex2 replaces expf
    const float scale2 = 0.20823512f;

    auto load_kv = [&](int st, int j0) {
#pragma unroll
        for (int rep = 0; rep < 3; rep++) {
            int i = tid + 256 * rep;
            if (i < HD * 8) {
                int d = i >> 3, c = (i & 7) * 8;
                cp16(cvta_s(Ksb + st * KVST + d * LDK + c), kbase + (size_t)d * SEQ + j0 + c);
            } else {
                int i2 = i - HD * 8;
                int d = i2 >> 3, c = (i2 & 7) * 8;
                cp16(cvta_s(Vsb + st * KVST + d * LDK + c), vbase + (size_t)d * SEQ + j0 + c);
            }
        }
        cp_commit();
    };

    load_kv(0, 0);
    load_kv(1, 64);

    for (int i = tid; i < HD * 16; i += 256) {
        int d = i >> 4, c = (i & 15) * 8;
        *reinterpret_cast<uint4*>(Qs + d * LDQ + c) =
            *reinterpret_cast<const uint4*>(qbase + (size_t)d * SEQ + q0g + c);
    }
    __syncthreads();

    uint32_t qa[3][4];
    {
        const int r_off = (lane & 7) + 8 * (lane >> 4);
        const int c_off = warp * 16 + 8 * ((lane >> 3) & 1);
#pragma unroll
        for (int kt = 0; kt < 3; kt++)
            ldmx4t(qa[kt], cvta_s(Qs + (kt * 16 + r_off) * LDQ + c_off));
    }

    float m0r = -1e30f, m1r = -1e30f;
    float l0r = 0.f, l1r = 0.f;
    float oa[6][4] = {};

    const int kb_r = (lane & 7) + 8 * ((lane >> 3) & 1);
    const int kb_c = 8 * (lane >> 4);
    const int vb_r = (lane & 7) + 8 * (lane >> 4);
    const int vb_c = 8 * ((lane >> 3) & 1);

    for (int it = 0; it < NJT; it++) {
        if (it == NJT - 1) cp_wait0(); else cp_wait1();
        __syncthreads();
        if (it + 2 < NJT) load_kv((it + 2) % 3, (it + 2) * 64);

        const __half* Kc = Ksb + (it % 3) * KVST;
        const __half* Vc = Vsb + (it % 3) * KVST;

        float s[8][4] = {};
#pragma unroll
        for (int kt = 0; kt < 3; kt++) {
            uint32_t bf[8][2];
#pragma unroll
            for (int ntp = 0; ntp < 4; ntp++) {
                uint32_t r[4];
                ldmx4t(r, cvta_s(Kc + (kt * 16 + kb_r) * LDK + ntp * 16 + kb_c));
                bf[2 * ntp][0] = r[0]; bf[2 * ntp][1] = r[1];
                bf[2 * ntp + 1][0] = r[2]; bf[2 * ntp + 1][1] = r[3];
            }
#pragma unroll
            for (int nt = 0; nt < 8; nt++)
                mma16816(s[nt], qa[kt], bf[nt][0], bf[nt][1]);
        }

        float mx0 = -1e30f, mx1 = -1e30f;
#pragma unroll
        for (int nt = 0; nt < 8; nt++) {
            mx0 = fmaxf(mx0, fmaxf(s[nt][0], s[nt][1]));
            mx1 = fmaxf(mx1, fmaxf(s[nt][2], s[nt][3]));
        }
        mx0 = fmaxf(mx0, __shfl_xor_sync(0xffffffffu, mx0, 1));
        mx0 = fmaxf(mx0, __shfl_xor_sync(0xffffffffu, mx0, 2));
        mx1 = fmaxf(mx1, __shfl_xor_sync(0xffffffffu, mx1, 1));
        mx1 = fmaxf(mx1, __shfl_xor_sync(0xffffffffu, mx1, 2));

        const float mn0 = fmaxf(m0r, mx0 * scale2);
        const float mn1 = fmaxf(m1r, mx1 * scale2);
        const float f0 = ex2f(m0r - mn0);
        const float f1 = ex2f(m1r - mn1);
        m0r = mn0; m1r = mn1;

        float sum0 = 0.f, sum1 = 0.f;
#pragma unroll
        for (int nt = 0; nt < 8; nt++) {
            s[nt][0] = ex2f(fmaf(s[nt][0], scale2, -mn0));
            s[nt][1] = ex2f(fmaf(s[nt][1], scale2, -mn0));
            s[nt][2] = ex2f(fmaf(s[nt][2], scale2, -mn1));
            s[nt][3] = ex2f(fmaf(s[nt][3], scale2, -mn1));
            sum0 += s[nt][0] + s[nt][1];
            sum1 += s[nt][2] + s[nt][3];
        }
        l0r = l0r * f0 + sum0;
        l1r = l1r * f1 + sum1;
#pragma unroll
        for (int nt2 = 0; nt2 < 6; nt2++) {
            oa[nt2][0] *= f0; oa[nt2][1] *= f0;
            oa[nt2][2] *= f1; oa[nt2][3] *= f1;
        }

#pragma unroll
        for (int t = 0; t < 4; t++) {
            uint32_t pa[4];
            pa[0] = pack_h2(s[2 * t][0],     s[2 * t][1]);
            pa[1] = pack_h2(s[2 * t][2],     s[2 * t][3]);
            pa[2] = pack_h2(s[2 * t + 1][0], s[2 * t + 1][1]);
            pa[3] = pack_h2(s[2 * t + 1][2], s[2 * t + 1][3]);
#pragma unroll
            for (int np = 0; np < 3; np++) {
                uint32_t r[4];
                ldmx4(r, cvta_s(Vc + (np * 16 + vb_r) * LDK + t * 16 + vb_c));
                mma16816(oa[2 * np],     pa, r[0], r[1]);
                mma16816(oa[2 * np + 1], pa, r[2], r[3]);
            }
        }
    }

    l0r += __shfl_xor_sync(0xffffffffu, l0r, 1);
    l0r += __shfl_xor_sync(0xffffffffu, l0r, 2);
    l1r += __shfl_xor_sync(0xffffffffu, l1r, 1);
    l1r += __shfl_xor_sync(0xffffffffu, l1r, 2);
    const float inv0 = 1.f / l0r, inv1 = 1.f / l1r;

    const int g = lane >> 2, tig = lane & 3;
    const int q_r = q0g + warp * 16 + g;
#pragma unroll
    for (int nt2 = 0; nt2 < 6; nt2++) {
        const int d = nt2 * 8 + 2 * tig;
        __half* dst = g_ao_h + ((size_t)bh * HD + d) * SEQ;
        dst[q_r]           = __float2half(oa[nt2][0] * inv0);
        dst[SEQ + q_r]     = __float2half(oa[nt2][1] * inv0);
        dst[q_r + 8]       = __float2half(oa[nt2][2] * inv1);
        dst[SEQ + q_r + 8] = __float2half(oa[nt2][3] * inv1);
    }
}

// ---------------------------------------------------------------------------
extern "C" void kernel_launch(void* const* d_in, const int* in_sizes, int n_in,
                              void* d_out, int out_size)
{
    const float* x      = (const float*)d_in[0];
    const float* w_qkv  = (const float*)d_in[1];
    const float* w_proj = (const float*)d_in[2];
    const float* b_proj = (const float*)d_in[3];
    float* out = (float*)d_out;

    static bool attr_set = false;
    if (!attr_set) {
        cudaFuncSetAttribute(attn_h_kernel,
                             cudaFuncAttributeMaxDynamicSharedMemorySize, ATTN_SMEM);
        cudaFuncSetAttribute(gemm_h_kernel<0>,
                             cudaFuncAttributeMaxDynamicSharedMemorySize, QKV_SMEM);
        cudaFuncSetAttribute(gemm_h_kernel<1>,
                             cudaFuncAttributeMaxDynamicSharedMemorySize, PROJ_SMEM);
        attr_set = true;
    }

    cvt_kernel<<<(N4_ALL + 255) / 256, 256>>>(x, w_qkv, w_proj);
    gemm_h_kernel<0><<<dim3(SEQ / 64, O3 / 128, BATCH), 256, QKV_SMEM>>>(nullptr, nullptr);
    attn_h_kernel<<<dim3(SEQ / 128, BATCH * NH), 256, ATTN_SMEM>>>();
    gemm_h_kernel<1><<<dim3(SEQ / 64, CH / 64, BATCH), 128, PROJ_SMEM>>>(b_proj, out);
}

// round 10
// speedup vs baseline: 9.8943x; 1.0634x over previous
#include <cuda_runtime.h>
#include <cuda_fp16.h>
#include <cstdint>

#define BATCH 8
#define CH    384
#define NH    8
#define HD    48
#define SEQ   1024
#define O3    1152   // 3*CH

// fp16 scratch (device globals — allocation-free per harness rules)
__device__ __align__(16) __half g_x_h    [(size_t)BATCH * CH * SEQ];
__device__ __align__(16) __half g_wqkv_h [(size_t)O3 * CH];
__device__ __align__(16) __half g_wproj_h[(size_t)CH * CH];
__device__ __align__(16) __half g_qkv_h  [(size_t)BATCH * O3 * SEQ];
__device__ __align__(16) __half g_ao_h   [(size_t)BATCH * CH * SEQ];

// ---------------------------------------------------------------------------
// PTX helpers
// ---------------------------------------------------------------------------
__device__ __forceinline__ uint32_t cvta_s(const void* p) {
    return (uint32_t)__cvta_generic_to_shared(p);
}
__device__ __forceinline__ void ldmx4(uint32_t* r, uint32_t a) {
    asm volatile("ldmatrix.sync.aligned.m8n8.x4.shared.b16 {%0,%1,%2,%3},[%4];"
        : "=r"(r[0]), "=r"(r[1]), "=r"(r[2]), "=r"(r[3]) : "r"(a));
}
__device__ __forceinline__ void ldmx4t(uint32_t* r, uint32_t a) {
    asm volatile("ldmatrix.sync.aligned.m8n8.x4.trans.shared.b16 {%0,%1,%2,%3},[%4];"
        : "=r"(r[0]), "=r"(r[1]), "=r"(r[2]), "=r"(r[3]) : "r"(a));
}
__device__ __forceinline__ void mma16816(float* c, const uint32_t* a,
                                         uint32_t b0, uint32_t b1) {
    asm volatile(
        "mma.sync.aligned.m16n8k16.row.col.f32.f16.f16.f32 "
        "{%0,%1,%2,%3},{%4,%5,%6,%7},{%8,%9},{%0,%1,%2,%3};"
        : "+f"(c[0]), "+f"(c[1]), "+f"(c[2]), "+f"(c[3])
        : "r"(a[0]), "r"(a[1]), "r"(a[2]), "r"(a[3]), "r"(b0), "r"(b1));
}
__device__ __forceinline__ uint32_t pack_h2(float lo, float hi) {
    __half2 h = __floats2half2_rn(lo, hi);
    return *reinterpret_cast<uint32_t*>(&h);
}
__device__ __forceinline__ float ex2f(float x) {
    float y;
    asm("ex2.approx.f32 %0, %1;" : "=f"(y) : "f"(x));
    return y;
}
// exp2 of a pair in one MUFU op; result packed fp16x2 (lo = first arg)
__device__ __forceinline__ uint32_t pexp2(float a, float b, float mn, float sc) {
    float e0 = fmaf(a, sc, -mn);
    float e1 = fmaf(b, sc, -mn);
    uint32_t h;
    asm("cvt.rn.f16x2.f32 %0, %1, %2;" : "=r"(h) : "f"(e1), "f"(e0));  // lo=e0
    asm("ex2.approx.f16x2 %0, %0;" : "+r"(h));
    return h;
}
__device__ __forceinline__ void cp16(uint32_t s, const void* g) {
    asm volatile("cp.async.cg.shared.global [%0], [%1], 16;" :: "r"(s), "l"(g));
}
__device__ __forceinline__ void cp_commit() { asm volatile("cp.async.commit_group;"); }
__device__ __forceinline__ void cp_wait1()  { asm volatile("cp.async.wait_group 1;"); }
__device__ __forceinline__ void cp_wait0()  { asm volatile("cp.async.wait_group 0;"); }

// ---------------------------------------------------------------------------
// fp32 -> fp16 pre-conversion of x, w_qkv, w_proj
// ---------------------------------------------------------------------------
#define N4_X  (BATCH * CH * SEQ / 4)
#define N4_WQ (O3 * CH / 4)
#define N4_WP (CH * CH / 4)
#define N4_ALL (N4_X + N4_WQ + N4_WP)

__global__ __launch_bounds__(256)
void cvt_kernel(const float* __restrict__ x,
                const float* __restrict__ wq,
                const float* __restrict__ wp)
{
    int i = blockIdx.x * 256 + threadIdx.x;
    if (i >= N4_ALL) return;
    const float4* src;
    __half* dst;
    int off;
    if (i < N4_X)              { src = (const float4*)x;  dst = g_x_h;     off = i; }
    else if (i < N4_X + N4_WQ) { src = (const float4*)wq; dst = g_wqkv_h;  off = i - N4_X; }
    else                       { src = (const float4*)wp; dst = g_wproj_h; off = i - N4_X - N4_WQ; }
    float4 v = src[off];
    *reinterpret_cast<uint2*>(dst + 4 * (size_t)off) =
        make_uint2(pack_h2(v.x, v.y), pack_h2(v.z, v.w));
}

// ---------------------------------------------------------------------------
// fp16 GEMM (identical to passing R8 code): BK=64, 3-stage cp.async ring,
// fragment double-buffering. IS_PROJ=0: BM=128/256thr; IS_PROJ=1: BM=64/128thr.
// ---------------------------------------------------------------------------
#define GEMM_LD 72

template<int IS_PROJ>
__global__ __launch_bounds__(IS_PROJ ? 128 : 256)
void gemm_h_kernel(const float* __restrict__ bias, float* __restrict__ Out32)
{
    constexpr int BM = IS_PROJ ? 64 : 128;
    constexpr int T  = IS_PROJ ? 128 : 256;
    constexpr int BK = 64, BN = 64;
    constexpr int LD = GEMM_LD;
    constexpr int A_H = BM * LD;
    constexpr int B_H = BK * LD;
    constexpr int ST_H = A_H + B_H;
    constexpr int NIT = CH / BK;
    constexpr int M_CH = IS_PROJ ? CH : O3;

    extern __shared__ __align__(16) __half gsm[];

    const __half* gA = IS_PROJ ? g_wproj_h : g_wqkv_h;
    const __half* gB = (IS_PROJ ? g_ao_h : g_x_h) + (size_t)blockIdx.z * CH * SEQ;

    const int b   = blockIdx.z;
    const int o0  = blockIdx.y * BM;
    const int p0  = blockIdx.x * BN;
    const int tid = threadIdx.x;
    const int warp = tid >> 5, lane = tid & 31;
    const int wm = warp >> 1, wn = warp & 1;

    const int a_r = lane & 15;
    const int a_c = 8 * (lane >> 4);
    const int b_r = (lane & 7) + 8 * ((lane >> 3) & 1);
    const int b_c = 8 * (lane >> 4);

    float acc[2][4][4] = {};

    auto load_stage = [&](int st, int k0) {
        __half* S = gsm + st * ST_H;
#pragma unroll
        for (int j = 0; j < 4; j++) {
            int i = tid + T * j;
            int row = i >> 3, c8 = i & 7;
            cp16(cvta_s(S + row * LD + c8 * 8),
                 gA + (size_t)(o0 + row) * CH + k0 + c8 * 8);
        }
#pragma unroll
        for (int j = 0; j < (IS_PROJ ? 4 : 2); j++) {
            int i = tid + T * j;
            int row = i >> 3, c8 = i & 7;
            cp16(cvta_s(S + A_H + row * LD + c8 * 8),
                 gB + (size_t)(k0 + row) * SEQ + p0 + c8 * 8);
        }
        cp_commit();
    };

    load_stage(0, 0);
    load_stage(1, BK);

    uint32_t af[2][2][4];
    uint32_t bf[2][4][2];

    for (int it = 0; it < NIT; it++) {
        if (it == NIT - 1) cp_wait0(); else cp_wait1();
        __syncthreads();
        if (it + 2 < NIT) load_stage((it + 2) % 3, (it + 2) * BK);

        const __half* Ac = gsm + (it % 3) * ST_H;
        const __half* Bc = Ac + A_H;

        auto ldfrag = [&](int slot, int kk) {
#pragma unroll
            for (int mt = 0; mt < 2; mt++)
                ldmx4(af[slot][mt],
                      cvta_s(Ac + (wm * 32 + mt * 16 + a_r) * LD + kk + a_c));
#pragma unroll
            for (int ntp = 0; ntp < 2; ntp++) {
                uint32_t r[4];
                ldmx4t(r, cvta_s(Bc + (kk + b_r) * LD + wn * 32 + ntp * 16 + b_c));
                bf[slot][2 * ntp][0] = r[0]; bf[slot][2 * ntp][1] = r[1];
                bf[slot][2 * ntp + 1][0] = r[2]; bf[slot][2 * ntp + 1][1] = r[3];
            }
        };

        ldfrag(0, 0);
#pragma unroll
        for (int ki = 0; ki < 4; ki++) {
            if (ki < 3) ldfrag((ki + 1) & 1, (ki + 1) * 16);
            const int c = ki & 1;
#pragma unroll
            for (int mt = 0; mt < 2; mt++)
#pragma unroll
                for (int nt = 0; nt < 4; nt++)
                    mma16816(acc[mt][nt], af[c][mt], bf[c][nt][0], bf[c][nt][1]);
        }
    }

    const int g = lane >> 2, tig = lane & 3;
#pragma unroll
    for (int mt = 0; mt < 2; mt++) {
        const int o_r = o0 + wm * 32 + mt * 16 + g;
#pragma unroll
        for (int nt = 0; nt < 4; nt++) {
            const int p_c = p0 + wn * 32 + nt * 8 + 2 * tig;
            if (!IS_PROJ) {
                __half* dst = g_qkv_h + ((size_t)b * M_CH + o_r) * SEQ + p_c;
                *reinterpret_cast<uint32_t*>(dst) =
                    pack_h2(acc[mt][nt][0], acc[mt][nt][1]);
                *reinterpret_cast<uint32_t*>(dst + 8 * SEQ) =
                    pack_h2(acc[mt][nt][2], acc[mt][nt][3]);
            } else {
                const float bv0 = bias[o_r], bv1 = bias[o_r + 8];
                float* dst = Out32 + ((size_t)b * M_CH + o_r) * SEQ + p_c;
                *reinterpret_cast<float2*>(dst) =
                    make_float2(acc[mt][nt][0] + bv0, acc[mt][nt][1] + bv0);
                *reinterpret_cast<float2*>(dst + 8 * SEQ) =
                    make_float2(acc[mt][nt][2] + bv1, acc[mt][nt][3] + bv1);
            }
        }
    }
}

#define QKV_SMEM  (3 * (128 * GEMM_LD + 64 * GEMM_LD) * 2)
#define PROJ_SMEM (3 * (64 * GEMM_LD + 64 * GEMM_LD) * 2)

// ---------------------------------------------------------------------------
// Flash attention: 3-stage cp.async K/V ring; f16x2 packed exp; l-sum via a
// constant ones-column in the PV mma (fp32-accurate, rescales for free).
// Per CTA: one (b,h), 128 queries (8 warps x 16 rows), key tiles of 64.
// ---------------------------------------------------------------------------
#define LDQ 136
#define LDK 72
#define ATTN_SMEM (HD * LDQ * 2 + 6 * HD * LDK * 2 + 512)   // + ones tile

__global__ __launch_bounds__(256)
void attn_h_kernel()
{
    constexpr int NJT = SEQ / 64;
    constexpr int KVST = HD * LDK;

    extern __shared__ __align__(16) __half dsm[];
    __half* Qs = dsm;
    __half* Ksb = dsm + HD * LDQ;
    __half* Vsb = Ksb + 3 * KVST;
    __half* Vones = Vsb + 3 * KVST;   // 16 rows x 16 halves; row 0 = 1.0

    const int bh = blockIdx.y, qb = blockIdx.x;
    const int tid = threadIdx.x, warp = tid >> 5, lane = tid & 31;
    const int b = bh >> 3, h = bh & 7;

    const __half* qbase = g_qkv_h + ((size_t)b * O3 + h * HD) * SEQ;
    const __half* kbase = qbase + (size_t)CH * SEQ;
    const __half* vbase = qbase + (size_t)2 * CH * SEQ;
    const int q0g = qb * 128;

    const float scale2 = 0.20823512f;   // 48^-0.5 * log2(e)

    auto load_kv = [&](int st, int j0) {
#pragma unroll
        for (int rep = 0; rep < 3; rep++) {
            int i = tid + 256 * rep;
            if (i < HD * 8) {
                int d = i >> 3, c = (i & 7) * 8;
                cp16(cvta_s(Ksb + st * KVST + d * LDK + c), kbase + (size_t)d * SEQ + j0 + c);
            } else {
                int i2 = i - HD * 8;
                int d = i2 >> 3, c = (i2 & 7) * 8;
                cp16(cvta_s(Vsb + st * KVST + d * LDK + c), vbase + (size_t)d * SEQ + j0 + c);
            }
        }
        cp_commit();
    };

    load_kv(0, 0);
    load_kv(1, 64);

    // Q tile + ones tile init
    for (int i = tid; i < HD * 16; i += 256) {
        int d = i >> 4, c = (i & 15) * 8;
        *reinterpret_cast<uint4*>(Qs + d * LDQ + c) =
            *reinterpret_cast<const uint4*>(qbase + (size_t)d * SEQ + q0g + c);
    }
    if (tid < 256) {
        int i = tid;
        if (i < 16 * 16) Vones[i] = (i < 16) ? __float2half(1.f) : __float2half(0.f);
    }
    __syncthreads();

    uint32_t qa[3][4];
    {
        const int r_off = (lane & 7) + 8 * (lane >> 4);
        const int c_off = warp * 16 + 8 * ((lane >> 3) & 1);
#pragma unroll
        for (int kt = 0; kt < 3; kt++)
            ldmx4t(qa[kt], cvta_s(Qs + (kt * 16 + r_off) * LDQ + c_off));
    }

    const int kb_r = (lane & 7) + 8 * ((lane >> 3) & 1);
    const int kb_c = 8 * (lane >> 4);
    const int vb_r = (lane & 7) + 8 * (lane >> 4);
    const int vb_c = 8 * ((lane >> 3) & 1);

    // constant ones B-fragment (same for every j-chunk and stage)
    uint32_t vob[2];
    {
        uint32_t r[4];
        ldmx4(r, cvta_s(Vones + vb_r * 16 + vb_c));
        vob[0] = r[0]; vob[1] = r[1];
    }

    float m0r = -1e30f, m1r = -1e30f;
    float oa[7][4] = {};   // [6] column 48 = running row-sum l

    for (int it = 0; it < NJT; it++) {
        if (it == NJT - 1) cp_wait0(); else cp_wait1();
        __syncthreads();
        if (it + 2 < NJT) load_kv((it + 2) % 3, (it + 2) * 64);

        const __half* Kc = Ksb + (it % 3) * KVST;
        const __half* Vc = Vsb + (it % 3) * KVST;

        // ---- S = Q K^T ----
        float s[8][4] = {};
#pragma unroll
        for (int kt = 0; kt < 3; kt++) {
            uint32_t bf[8][2];
#pragma unroll
            for (int ntp = 0; ntp < 4; ntp++) {
                uint32_t r[4];
                ldmx4t(r, cvta_s(Kc + (kt * 16 + kb_r) * LDK + ntp * 16 + kb_c));
                bf[2 * ntp][0] = r[0]; bf[2 * ntp][1] = r[1];
                bf[2 * ntp + 1][0] = r[2]; bf[2 * ntp + 1][1] = r[3];
            }
#pragma unroll
            for (int nt = 0; nt < 8; nt++)
                mma16816(s[nt], qa[kt], bf[nt][0], bf[nt][1]);
        }

        // ---- online softmax: max + rescale ----
        float mx0 = -1e30f, mx1 = -1e30f;
#pragma unroll
        for (int nt = 0; nt < 8; nt++) {
            mx0 = fmaxf(mx0, fmaxf(s[nt][0], s[nt][1]));
            mx1 = fmaxf(mx1, fmaxf(s[nt][2], s[nt][3]));
        }
        mx0 = fmaxf(mx0, __shfl_xor_sync(0xffffffffu, mx0, 1));
        mx0 = fmaxf(mx0, __shfl_xor_sync(0xffffffffu, mx0, 2));
        mx1 = fmaxf(mx1, __shfl_xor_sync(0xffffffffu, mx1, 1));
        mx1 = fmaxf(mx1, __shfl_xor_sync(0xffffffffu, mx1, 2));

        const float mn0 = fmaxf(m0r, mx0 * scale2);
        const float mn1 = fmaxf(m1r, mx1 * scale2);
        const float f0 = ex2f(m0r - mn0);
        const float f1 = ex2f(m1r - mn1);
        m0r = mn0; m1r = mn1;

#pragma unroll
        for (int nt2 = 0; nt2 < 7; nt2++) {
            oa[nt2][0] *= f0; oa[nt2][1] *= f0;
            oa[nt2][2] *= f1; oa[nt2][3] *= f1;
        }

        // ---- P fragments via packed exp; O += P V; l via ones column ----
#pragma unroll
        for (int t = 0; t < 4; t++) {
            uint32_t pa[4];
            pa[0] = pexp2(s[2 * t][0],     s[2 * t][1],     mn0, scale2);
            pa[1] = pexp2(s[2 * t][2],     s[2 * t][3],     mn1, scale2);
            pa[2] = pexp2(s[2 * t + 1][0], s[2 * t + 1][1], mn0, scale2);
            pa[3] = pexp2(s[2 * t + 1][2], s[2 * t + 1][3], mn1, scale2);
#pragma unroll
            for (int np = 0; np < 3; np++) {
                uint32_t r[4];
                ldmx4(r, cvta_s(Vc + (np * 16 + vb_r) * LDK + t * 16 + vb_c));
                mma16816(oa[2 * np],     pa, r[0], r[1]);
                mma16816(oa[2 * np + 1], pa, r[2], r[3]);
            }
            mma16816(oa[6], pa, vob[0], vob[1]);   // row-sum column
        }
    }

    // ---- epilogue: l lives in oa[6][0]/oa[6][2] of the tig==0 lane ----
    const float l0r = __shfl_sync(0xffffffffu, oa[6][0], lane & 28);
    const float l1r = __shfl_sync(0xffffffffu, oa[6][2], lane & 28);
    const float inv0 = 1.f / l0r, inv1 = 1.f / l1r;

    const int g = lane >> 2, tig = lane & 3;
    const int q_r = q0g + warp * 16 + g;
#pragma unroll
    for (int nt2 = 0; nt2 < 6; nt2++) {
        const int d = nt2 * 8 + 2 * tig;
        __half* dst = g_ao_h + ((size_t)bh * HD + d) * SEQ;
        dst[q_r]           = __float2half(oa[nt2][0] * inv0);
        dst[SEQ + q_r]     = __float2half(oa[nt2][1] * inv0);
        dst[q_r + 8]       = __float2half(oa[nt2][2] * inv1);
        dst[SEQ + q_r + 8] = __float2half(oa[nt2][3] * inv1);
    }
}

// ---------------------------------------------------------------------------
extern "C" void kernel_launch(void* const* d_in, const int* in_sizes, int n_in,
                              void* d_out, int out_size)
{
    const float* x      = (const float*)d_in[0];
    const float* w_qkv  = (const float*)d_in[1];
    const float* w_proj = (const float*)d_in[2];
    const float* b_proj = (const float*)d_in[3];
    float* out = (float*)d_out;

    static bool attr_set = false;
    if (!attr_set) {
        cudaFuncSetAttribute(attn_h_kernel,
                             cudaFuncAttributeMaxDynamicSharedMemorySize, ATTN_SMEM);
        cudaFuncSetAttribute(gemm_h_kernel<0>,
                             cudaFuncAttributeMaxDynamicSharedMemorySize, QKV_SMEM);
        cudaFuncSetAttribute(gemm_h_kernel<1>,
                             cudaFuncAttributeMaxDynamicSharedMemorySize, PROJ_SMEM);
        attr_set = true;
    }

    cvt_kernel<<<(N4_ALL + 255) / 256, 256>>>(x, w_qkv, w_proj);
    gemm_h_kernel<0><<<dim3(SEQ / 64, O3 / 128, BATCH), 256, QKV_SMEM>>>(nullptr, nullptr);
    attn_h_kernel<<<dim3(SEQ / 128, BATCH * NH), 256, ATTN_SMEM>>>();
    gemm_h_kernel<1><<<dim3(SEQ / 64, CH / 64, BATCH), 128, PROJ_SMEM>>>(b_proj, out);
}